// round 3
// baseline (speedup 1.0000x reference)
#include <cuda_runtime.h>
#include <cuda_bf16.h>
#include <cstdint>
#include <cstdio>

#define BSZ 4096
#define RR 36
#define TT 32
#define LL 1024
#define LK 256

// ---------------- scratch (__device__ globals; no allocations allowed) ----------------
__device__ __nv_bfloat16 g_sHi[BSZ * LL];   // bf16(s)
__device__ __nv_bfloat16 g_sLo[BSZ * LL];   // bf16(s - hi)
__device__ __nv_bfloat16 g_s2[BSZ * LL];    // bf16(s*s)
__device__ __nv_bfloat16 g_gHi[BSZ * LL];   // bf16(gate * c_hat)
__device__ __nv_bfloat16 g_gLo[BSZ * LL];   // bf16(residual)
__device__ __nv_bfloat16 g_hh[BSZ * LL];    // bf16(gate*gate)
__device__ float g_repr[BSZ * LK];
__device__ float g_invn[BSZ];

// ---------------- K1: s = img.sum(axis=1), emit bf16 splits ----------------
__global__ void k_sum(const float* __restrict__ img) {
    const int b = blockIdx.x, t = threadIdx.x;            // 256 threads, 4 cols each
    const float4* p = reinterpret_cast<const float4*>(img + (size_t)b * RR * LL) + t;
    float4 acc = make_float4(0.f, 0.f, 0.f, 0.f);
#pragma unroll
    for (int r = 0; r < RR; ++r) {
        float4 v = p[r * (LL / 4)];
        acc.x += v.x; acc.y += v.y; acc.z += v.z; acc.w += v.w;
    }
    const size_t o = (size_t)b * LL + t * 4;
    float s[4] = {acc.x, acc.y, acc.z, acc.w};
#pragma unroll
    for (int c = 0; c < 4; ++c) {
        __nv_bfloat16 hi = __float2bfloat16(s[c]);
        __nv_bfloat16 lo = __float2bfloat16(s[c] - __bfloat162float(hi));
        __nv_bfloat16 s2 = __float2bfloat16(s[c] * s[c]);
        g_sHi[o + c] = hi;
        g_sLo[o + c] = lo;
        g_s2[o + c]  = s2;
    }
}

// ---------------- K2: inv_norm of cap0 rows ----------------
__global__ void k_norm(const float* __restrict__ cap) {
    const int b = blockIdx.x, t = threadIdx.x;            // 256 threads
    const float4 v = reinterpret_cast<const float4*>(cap + (size_t)b * TT * LL)[t];
    float ss = v.x * v.x + v.y * v.y + v.z * v.z + v.w * v.w;
#pragma unroll
    for (int o = 16; o; o >>= 1) ss += __shfl_xor_sync(0xffffffffu, ss, o);
    __shared__ float red[8];
    if ((t & 31) == 0) red[t >> 5] = ss;
    __syncthreads();
    if (t == 0) {
        float tot = 0.f;
#pragma unroll
        for (int w = 0; w < 8; ++w) tot += red[w];
        g_invn[b] = rsqrtf(tot);
    }
}

// ---------------- K3: cap_repr = cap0 @ W_red^T + b_red ----------------
__global__ __launch_bounds__(256) void k_repr(const float* __restrict__ cap,
                                              const float* __restrict__ Wred,
                                              const float* __restrict__ bred) {
    __shared__ float sc[8][LL];                           // 32 KB
    const int b0 = blockIdx.x * 8, t = threadIdx.x;       // thread t = output feature
#pragma unroll
    for (int bb = 0; bb < 8; ++bb)
        reinterpret_cast<float4*>(sc[bb])[t] =
            reinterpret_cast<const float4*>(cap + (size_t)(b0 + bb) * TT * LL)[t];
    __syncthreads();

    float acc[8] = {0.f, 0.f, 0.f, 0.f, 0.f, 0.f, 0.f, 0.f};
    const float4* w = reinterpret_cast<const float4*>(Wred + (size_t)t * LL);
    for (int k4 = 0; k4 < LL / 4; ++k4) {
        const float4 wv = w[k4];
#pragma unroll
        for (int bb = 0; bb < 8; ++bb) {
            const float4 cv = reinterpret_cast<const float4*>(sc[bb])[k4];  // broadcast
            acc[bb] += wv.x * cv.x + wv.y * cv.y + wv.z * cv.z + wv.w * cv.w;
        }
    }
    const float bias = bred[t];
#pragma unroll
    for (int bb = 0; bb < 8; ++bb)
        g_repr[(size_t)(b0 + bb) * LK + t] = acc[bb] + bias;
}

// ---------------- K4: gate = sigmoid(repr @ W_kp^T + b_kp); emit g/h splits ----------------
__global__ __launch_bounds__(256) void k_gate(const float* __restrict__ cap,
                                              const float* __restrict__ Wkp,
                                              const float* __restrict__ bkp) {
    __shared__ float sr[16][LK];                          // 16 KB
    const int b0 = blockIdx.x * 16, t = threadIdx.x;
#pragma unroll
    for (int bb = 0; bb < 16; ++bb)
        sr[bb][t] = g_repr[(size_t)(b0 + bb) * LK + t];
    __syncthreads();

    float acc[16][4];
#pragma unroll
    for (int bb = 0; bb < 16; ++bb)
#pragma unroll
        for (int q = 0; q < 4; ++q) acc[bb][q] = 0.f;

    for (int k4 = 0; k4 < LK / 4; ++k4) {
        float4 wv[4];
#pragma unroll
        for (int q = 0; q < 4; ++q)
            wv[q] = reinterpret_cast<const float4*>(Wkp + (size_t)(t + 256 * q) * LK)[k4];
#pragma unroll
        for (int bb = 0; bb < 16; ++bb) {
            const float4 rv = reinterpret_cast<const float4*>(sr[bb])[k4]; // broadcast
#pragma unroll
            for (int q = 0; q < 4; ++q)
                acc[bb][q] += wv[q].x * rv.x + wv[q].y * rv.y + wv[q].z * rv.z + wv[q].w * rv.w;
        }
    }
#pragma unroll
    for (int q = 0; q < 4; ++q) {
        const int l = t + 256 * q;
        const float bias = bkp[l];
#pragma unroll
        for (int bb = 0; bb < 16; ++bb) {
            const int b = b0 + bb;
            const float z = acc[bb][q] + bias;
            const float gate = 1.0f / (1.0f + expf(-z));
            const float c0 = cap[(size_t)b * TT * LL + l];
            const float gh_f = gate * c0 * g_invn[b];
            const __nv_bfloat16 gh = __float2bfloat16(gh_f);
            const __nv_bfloat16 gl = __float2bfloat16(gh_f - __bfloat162float(gh));
            const __nv_bfloat16 hh = __float2bfloat16(gate * gate);
            const size_t o = (size_t)b * LL + l;
            g_gHi[o] = gh; g_gLo[o] = gl; g_hh[o] = hh;
        }
    }
}

// ---------------- K5: fused dual GEMM  out[i,j] = (s_i . g_j) * rsqrt(s2_i . h_j) ----------------
#define KC 16
#define SSTRIDE 24                 // 16 used + 8 pad bf16 -> 48B rows, conflict-free b32 frag loads
#define ATILE (128 * SSTRIDE)      // 3072 elems per array tile
#define SSTAGE (6 * ATILE)         // 18432 elems per stage (36 KB)
#define NKT (LL / KC)              // 64

__device__ __forceinline__ void cp16(__nv_bfloat16* s, const __nv_bfloat16* g) {
    uint32_t sa = (uint32_t)__cvta_generic_to_shared(s);
    asm volatile("cp.async.cg.shared.global [%0], [%1], 16;" ::"r"(sa), "l"(g));
}
__device__ __forceinline__ uint32_t ld32(const __nv_bfloat16* p) {
    return *reinterpret_cast<const uint32_t*>(p);
}
__device__ __forceinline__ void mma_bf16(float d[4], const uint32_t a[4], const uint32_t b[2]) {
    asm volatile(
        "mma.sync.aligned.m16n8k16.row.col.f32.bf16.bf16.f32 "
        "{%0,%1,%2,%3}, {%4,%5,%6,%7}, {%8,%9}, {%0,%1,%2,%3};"
        : "+f"(d[0]), "+f"(d[1]), "+f"(d[2]), "+f"(d[3])
        : "r"(a[0]), "r"(a[1]), "r"(a[2]), "r"(a[3]), "r"(b[0]), "r"(b[1]));
}

__global__ __launch_bounds__(256, 1) void k_main(float* __restrict__ out) {
    extern __shared__ __nv_bfloat16 sm[];
    const int t = threadIdx.x;
    const int lane = t & 31, wid = t >> 5;
    const int wm = wid >> 2, wn = wid & 3;     // 2x4 warp grid, warp tile 64x32
    const int lr = lane >> 2, lc = lane & 3;
    const int i0 = blockIdx.y * 128, j0 = blockIdx.x * 128;

    float numer[4][4][4], denom[4][4][4];
#pragma unroll
    for (int a = 0; a < 4; ++a)
#pragma unroll
        for (int b = 0; b < 4; ++b)
#pragma unroll
            for (int c = 0; c < 4; ++c) { numer[a][b][c] = 0.f; denom[a][b][c] = 0.f; }

    // global->smem mapping: thread t loads one 16B chunk per array per stage
    const int grow = t >> 1, ghalf = t & 1;
    const size_t aoff = (size_t)(i0 + grow) * LL + ghalf * 8;
    const size_t boff = (size_t)(j0 + grow) * LL + ghalf * 8;
    const __nv_bfloat16* gA0 = g_sHi + aoff;
    const __nv_bfloat16* gA1 = g_sLo + aoff;
    const __nv_bfloat16* gA2 = g_s2 + aoff;
    const __nv_bfloat16* gB0 = g_gHi + boff;
    const __nv_bfloat16* gB1 = g_gLo + boff;
    const __nv_bfloat16* gB2 = g_hh + boff;
    __nv_bfloat16* sdst = sm + grow * SSTRIDE + ghalf * 8;

    // prologue: stage 0
    cp16(sdst + 0 * ATILE, gA0);
    cp16(sdst + 1 * ATILE, gA1);
    cp16(sdst + 2 * ATILE, gA2);
    cp16(sdst + 3 * ATILE, gB0);
    cp16(sdst + 4 * ATILE, gB1);
    cp16(sdst + 5 * ATILE, gB2);
    asm volatile("cp.async.commit_group;");

#pragma unroll 1
    for (int kt = 0; kt < NKT; ++kt) {
        const int st = kt & 1;
        if (kt + 1 < NKT) {
            const int ko = (kt + 1) * KC;
            __nv_bfloat16* sd = sdst + (st ^ 1) * SSTAGE;
            cp16(sd + 0 * ATILE, gA0 + ko);
            cp16(sd + 1 * ATILE, gA1 + ko);
            cp16(sd + 2 * ATILE, gA2 + ko);
            cp16(sd + 3 * ATILE, gB0 + ko);
            cp16(sd + 4 * ATILE, gB1 + ko);
            cp16(sd + 5 * ATILE, gB2 + ko);
            asm volatile("cp.async.commit_group;");
            asm volatile("cp.async.wait_group 1;");
        } else {
            asm volatile("cp.async.wait_group 0;");
        }
        __syncthreads();

        const __nv_bfloat16* sb = sm + st * SSTAGE;
        uint32_t bG0[4][2], bG1[4][2], bH[4][2];
#pragma unroll
        for (int nt = 0; nt < 4; ++nt) {
            const __nv_bfloat16* pb = sb + (wn * 32 + nt * 8 + lr) * SSTRIDE + lc * 2;
            bG0[nt][0] = ld32(pb + 3 * ATILE);  bG0[nt][1] = ld32(pb + 3 * ATILE + 8);
            bG1[nt][0] = ld32(pb + 4 * ATILE);  bG1[nt][1] = ld32(pb + 4 * ATILE + 8);
            bH[nt][0]  = ld32(pb + 5 * ATILE);  bH[nt][1]  = ld32(pb + 5 * ATILE + 8);
        }
#pragma unroll
        for (int mt = 0; mt < 4; ++mt) {
            const __nv_bfloat16* pa = sb + (wm * 64 + mt * 16 + lr) * SSTRIDE + lc * 2;
            uint32_t aH[4], aL[4], a2[4];
            aH[0] = ld32(pa);                 aH[1] = ld32(pa + 8 * SSTRIDE);
            aH[2] = ld32(pa + 8);             aH[3] = ld32(pa + 8 * SSTRIDE + 8);
            aL[0] = ld32(pa + ATILE);         aL[1] = ld32(pa + ATILE + 8 * SSTRIDE);
            aL[2] = ld32(pa + ATILE + 8);     aL[3] = ld32(pa + ATILE + 8 * SSTRIDE + 8);
            a2[0] = ld32(pa + 2 * ATILE);     a2[1] = ld32(pa + 2 * ATILE + 8 * SSTRIDE);
            a2[2] = ld32(pa + 2 * ATILE + 8); a2[3] = ld32(pa + 2 * ATILE + 8 * SSTRIDE + 8);
#pragma unroll
            for (int nt = 0; nt < 4; ++nt) {
                mma_bf16(numer[mt][nt], aH, bG0[nt]);   // s_hi * g_hi
                mma_bf16(numer[mt][nt], aL, bG0[nt]);   // s_lo * g_hi
                mma_bf16(numer[mt][nt], aH, bG1[nt]);   // s_hi * g_lo
                mma_bf16(denom[mt][nt], a2, bH[nt]);    // s2   * h
            }
        }
        __syncthreads();
    }

    // epilogue
#pragma unroll
    for (int mt = 0; mt < 4; ++mt)
#pragma unroll
        for (int nt = 0; nt < 4; ++nt) {
            const int i = i0 + wm * 64 + mt * 16 + lr;
            const int j = j0 + wn * 32 + nt * 8 + lc * 2;
            float2 v0, v1;
            v0.x = numer[mt][nt][0] * rsqrtf(denom[mt][nt][0]);
            v0.y = numer[mt][nt][1] * rsqrtf(denom[mt][nt][1]);
            v1.x = numer[mt][nt][2] * rsqrtf(denom[mt][nt][2]);
            v1.y = numer[mt][nt][3] * rsqrtf(denom[mt][nt][3]);
            *reinterpret_cast<float2*>(out + (size_t)i * BSZ + j) = v0;
            *reinterpret_cast<float2*>(out + (size_t)(i + 8) * BSZ + j) = v1;
        }
}

// ---------------- launch ----------------
extern "C" void kernel_launch(void* const* d_in, const int* in_sizes, int n_in,
                              void* d_out, int out_size) {
    (void)in_sizes; (void)n_in; (void)out_size;
    const float* img  = (const float*)d_in[0];
    const float* cap  = (const float*)d_in[1];
    // d_in[2] = lens : unused by the reference computation
    const float* Wred = (const float*)d_in[3];
    const float* bred = (const float*)d_in[4];
    const float* Wkp  = (const float*)d_in[5];
    const float* bkp  = (const float*)d_in[6];
    float* out = (float*)d_out;

    k_sum<<<BSZ, 256>>>(img);
    k_norm<<<BSZ, 256>>>(cap);
    k_repr<<<BSZ / 8, 256>>>(cap, Wred, bred);
    k_gate<<<BSZ / 16, 256>>>(cap, Wkp, bkp);

    cudaFuncSetAttribute(k_main, cudaFuncAttributeMaxDynamicSharedMemorySize,
                         2 * SSTAGE * (int)sizeof(__nv_bfloat16));
    k_main<<<dim3(BSZ / 128, BSZ / 128), 256, 2 * SSTAGE * (int)sizeof(__nv_bfloat16)>>>(out);
}

// round 5
// speedup vs baseline: 1.2321x; 1.2321x over previous
#include <cuda_runtime.h>
#include <cuda_bf16.h>
#include <cstdint>

#define BSZ 4096
#define RR 36
#define TT 32
#define LL 1024
#define LK 256

// ---------------- scratch (__device__ globals; no allocations allowed) ----------------
__device__ __nv_bfloat16 g_sHi[BSZ * LL];   // bf16(s)
__device__ __nv_bfloat16 g_sLo[BSZ * LL];   // bf16(s - hi)
__device__ __nv_bfloat16 g_s2[BSZ * LL];    // bf16(s*s)
__device__ __nv_bfloat16 g_gHi[BSZ * LL];   // bf16(gate * c_hat)
__device__ __nv_bfloat16 g_gLo[BSZ * LL];   // bf16(residual)
__device__ __nv_bfloat16 g_hh[BSZ * LL];    // bf16(gate*gate)
__device__ float g_repr[BSZ * LK];
__device__ float g_invn[BSZ];

// ---------------- helpers ----------------
__device__ __forceinline__ uint32_t smem_u32(const void* p) {
    uint32_t a;
    asm("{ .reg .u64 t; cvta.to.shared.u64 t, %1; cvt.u32.u64 %0, t; }" : "=r"(a) : "l"(p));
    return a;
}
__device__ __forceinline__ void cp16b(uint32_t sa, const void* g) {
    asm volatile("cp.async.cg.shared.global [%0], [%1], 16;" ::"r"(sa), "l"(g));
}
__device__ __forceinline__ void ldsm4(uint32_t r[4], uint32_t sa) {
    asm volatile("ldmatrix.sync.aligned.m8n8.x4.shared.b16 {%0,%1,%2,%3}, [%4];"
                 : "=r"(r[0]), "=r"(r[1]), "=r"(r[2]), "=r"(r[3]) : "r"(sa));
}
__device__ __forceinline__ void mma_bf16(float d[4], const uint32_t a[4],
                                         uint32_t b0, uint32_t b1) {
    asm volatile(
        "mma.sync.aligned.m16n8k16.row.col.f32.bf16.bf16.f32 "
        "{%0,%1,%2,%3}, {%4,%5,%6,%7}, {%8,%9}, {%0,%1,%2,%3};"
        : "+f"(d[0]), "+f"(d[1]), "+f"(d[2]), "+f"(d[3])
        : "r"(a[0]), "r"(a[1]), "r"(a[2]), "r"(a[3]), "r"(b0), "r"(b1));
}

// ---------------- K1: s = img.sum(axis=1), emit bf16 splits ----------------
__global__ void k_sum(const float* __restrict__ img) {
    const int b = blockIdx.x, t = threadIdx.x;
    const float4* p = reinterpret_cast<const float4*>(img + (size_t)b * RR * LL) + t;
    float4 acc = make_float4(0.f, 0.f, 0.f, 0.f);
#pragma unroll
    for (int r = 0; r < RR; ++r) {
        float4 v = p[r * (LL / 4)];
        acc.x += v.x; acc.y += v.y; acc.z += v.z; acc.w += v.w;
    }
    const size_t o = (size_t)b * LL + t * 4;
    float s[4] = {acc.x, acc.y, acc.z, acc.w};
#pragma unroll
    for (int c = 0; c < 4; ++c) {
        __nv_bfloat16 hi = __float2bfloat16(s[c]);
        __nv_bfloat16 lo = __float2bfloat16(s[c] - __bfloat162float(hi));
        __nv_bfloat16 s2 = __float2bfloat16(s[c] * s[c]);
        g_sHi[o + c] = hi;
        g_sLo[o + c] = lo;
        g_s2[o + c]  = s2;
    }
}

// ---------------- K2: inv_norm of cap0 rows ----------------
__global__ void k_norm(const float* __restrict__ cap) {
    const int b = blockIdx.x, t = threadIdx.x;
    const float4 v = reinterpret_cast<const float4*>(cap + (size_t)b * TT * LL)[t];
    float ss = v.x * v.x + v.y * v.y + v.z * v.z + v.w * v.w;
#pragma unroll
    for (int o = 16; o; o >>= 1) ss += __shfl_xor_sync(0xffffffffu, ss, o);
    __shared__ float red[8];
    if ((t & 31) == 0) red[t >> 5] = ss;
    __syncthreads();
    if (t == 0) {
        float tot = 0.f;
#pragma unroll
        for (int w = 0; w < 8; ++w) tot += red[w];
        g_invn[b] = rsqrtf(tot);
    }
}

// ---------------- K3: cap_repr = cap0 @ W_red^T + b_red ----------------
__global__ __launch_bounds__(256) void k_repr(const float* __restrict__ cap,
                                              const float* __restrict__ Wred,
                                              const float* __restrict__ bred) {
    __shared__ float sc[8][LL];
    const int b0 = blockIdx.x * 8, t = threadIdx.x;
#pragma unroll
    for (int bb = 0; bb < 8; ++bb)
        reinterpret_cast<float4*>(sc[bb])[t] =
            reinterpret_cast<const float4*>(cap + (size_t)(b0 + bb) * TT * LL)[t];
    __syncthreads();

    float acc[8] = {0.f, 0.f, 0.f, 0.f, 0.f, 0.f, 0.f, 0.f};
    const float4* w = reinterpret_cast<const float4*>(Wred + (size_t)t * LL);
    for (int k4 = 0; k4 < LL / 4; ++k4) {
        const float4 wv = w[k4];
#pragma unroll
        for (int bb = 0; bb < 8; ++bb) {
            const float4 cv = reinterpret_cast<const float4*>(sc[bb])[k4];
            acc[bb] += wv.x * cv.x + wv.y * cv.y + wv.z * cv.z + wv.w * cv.w;
        }
    }
    const float bias = bred[t];
#pragma unroll
    for (int bb = 0; bb < 8; ++bb)
        g_repr[(size_t)(b0 + bb) * LK + t] = acc[bb] + bias;
}

// ---------------- K4: gate GEMM (128x128 tile, 8x8/thread), fused epilogue ----------------
__device__ __forceinline__ uint32_t pkbf2(__nv_bfloat16 a, __nv_bfloat16 b) {
    __nv_bfloat162 t = __halves2bfloat162(a, b);
    return *reinterpret_cast<uint32_t*>(&t);
}

__global__ __launch_bounds__(256) void k_gate(const float* __restrict__ cap,
                                              const float* __restrict__ Wkp,
                                              const float* __restrict__ bkp) {
    __shared__ float Rs[16][132];
    __shared__ float Ws[16][132];
    const int t = threadIdx.x;
    const int b0 = blockIdx.x * 128;
    const int l0 = blockIdx.y * 128;
    const int tr = t >> 4, tc = t & 15;     // 16x16 thread grid, 8x8 per thread
    const int lrow = t >> 1;                // 0..127
    const int lk = (t & 1) * 8;             // 0 or 8

    float acc[8][8];
#pragma unroll
    for (int a = 0; a < 8; ++a)
#pragma unroll
        for (int b = 0; b < 8; ++b) acc[a][b] = 0.f;

    const float* gr = g_repr + (size_t)(b0 + lrow) * LK + lk;
    const float* gw = Wkp + (size_t)(l0 + lrow) * LK + lk;

    for (int kc = 0; kc < LK; kc += 16) {
        const float4 r0 = *reinterpret_cast<const float4*>(gr + kc);
        const float4 r1 = *reinterpret_cast<const float4*>(gr + kc + 4);
        const float4 w0 = *reinterpret_cast<const float4*>(gw + kc);
        const float4 w1 = *reinterpret_cast<const float4*>(gw + kc + 4);
        __syncthreads();
        Rs[lk + 0][lrow] = r0.x; Rs[lk + 1][lrow] = r0.y; Rs[lk + 2][lrow] = r0.z; Rs[lk + 3][lrow] = r0.w;
        Rs[lk + 4][lrow] = r1.x; Rs[lk + 5][lrow] = r1.y; Rs[lk + 6][lrow] = r1.z; Rs[lk + 7][lrow] = r1.w;
        Ws[lk + 0][lrow] = w0.x; Ws[lk + 1][lrow] = w0.y; Ws[lk + 2][lrow] = w0.z; Ws[lk + 3][lrow] = w0.w;
        Ws[lk + 4][lrow] = w1.x; Ws[lk + 5][lrow] = w1.y; Ws[lk + 6][lrow] = w1.z; Ws[lk + 7][lrow] = w1.w;
        __syncthreads();
#pragma unroll
        for (int k = 0; k < 16; ++k) {
            float av[8], bv[8];
            *reinterpret_cast<float4*>(av)     = *reinterpret_cast<const float4*>(&Rs[k][tr * 8]);
            *reinterpret_cast<float4*>(av + 4) = *reinterpret_cast<const float4*>(&Rs[k][tr * 8 + 4]);
            *reinterpret_cast<float4*>(bv)     = *reinterpret_cast<const float4*>(&Ws[k][tc * 8]);
            *reinterpret_cast<float4*>(bv + 4) = *reinterpret_cast<const float4*>(&Ws[k][tc * 8 + 4]);
#pragma unroll
            for (int a = 0; a < 8; ++a)
#pragma unroll
                for (int b = 0; b < 8; ++b) acc[a][b] += av[a] * bv[b];
        }
    }

    // epilogue: sigmoid + c_hat combine + bf16 splits, packed 16B stores
    float bias[8];
#pragma unroll
    for (int ci = 0; ci < 8; ++ci) bias[ci] = bkp[l0 + tc * 8 + ci];

#pragma unroll
    for (int ri = 0; ri < 8; ++ri) {
        const int b = b0 + tr * 8 + ri;
        const float inv = g_invn[b];
        const float* crow = cap + (size_t)b * TT * LL + l0 + tc * 8;
        uint32_t pg[4], pl[4], ph[4];
#pragma unroll
        for (int cp = 0; cp < 4; ++cp) {
            __nv_bfloat16 gh2[2], gl2[2], hh2[2];
#pragma unroll
            for (int e = 0; e < 2; ++e) {
                const int ci = cp * 2 + e;
                const float z = acc[ri][ci] + bias[ci];
                const float gate = 1.0f / (1.0f + expf(-z));
                const float gh_f = gate * crow[ci] * inv;
                gh2[e] = __float2bfloat16(gh_f);
                gl2[e] = __float2bfloat16(gh_f - __bfloat162float(gh2[e]));
                hh2[e] = __float2bfloat16(gate * gate);
            }
            pg[cp] = pkbf2(gh2[0], gh2[1]);
            pl[cp] = pkbf2(gl2[0], gl2[1]);
            ph[cp] = pkbf2(hh2[0], hh2[1]);
        }
        const size_t o = (size_t)b * LL + l0 + tc * 8;
        *reinterpret_cast<uint4*>(g_gHi + o) = make_uint4(pg[0], pg[1], pg[2], pg[3]);
        *reinterpret_cast<uint4*>(g_gLo + o) = make_uint4(pl[0], pl[1], pl[2], pl[3]);
        *reinterpret_cast<uint4*>(g_hh + o)  = make_uint4(ph[0], ph[1], ph[2], ph[3]);
    }
}

// ---------------- K5: fused dual GEMM, ldmatrix + mma.sync ----------------
#define KC 32
#define ASTRIDE 40                    // bf16 elems per smem row (80B: 64 used + 16 pad)
#define TILEE (128 * ASTRIDE)         // 5120 elems per array tile
#define STAGEE (6 * TILEE)            // 30720 elems per stage (61440 B)
#define NKT (LL / KC)                 // 32
#define SMEM_MAIN (2 * STAGEE * (int)sizeof(__nv_bfloat16))   // 122880 B

__device__ __forceinline__ void load_stage_m(uint32_t sstage, int i0, int j0, int k0, int t) {
    const int c = t & 3;              // 16B chunk within 64B of k
    const int r = t >> 2;             // row 0..63 (also +64)
    const __nv_bfloat16* srcs[6] = {g_sHi, g_sLo, g_s2, g_gHi, g_gLo, g_hh};
#pragma unroll
    for (int a = 0; a < 6; ++a) {
        const int base = (a < 3) ? i0 : j0;
        const __nv_bfloat16* g = srcs[a] + (size_t)(base + r) * LL + k0 + c * 8;
        const uint32_t sa = sstage + a * TILEE * 2 + r * (ASTRIDE * 2) + c * 16;
        cp16b(sa, g);
        cp16b(sa + 64 * (ASTRIDE * 2), g + (size_t)64 * LL);
    }
}

__global__ __launch_bounds__(256, 1) void k_main(float* __restrict__ out) {
    extern __shared__ __nv_bfloat16 sm[];
    const uint32_t sbase = smem_u32(sm);
    const int t = threadIdx.x;
    const int lane = t & 31, wid = t >> 5;
    const int wm = wid >> 2, wn = wid & 3;     // 2x4 warp grid, warp tile 64x32
    const int lr = lane >> 2, lc = lane & 3;
    const int i0 = blockIdx.y * 128, j0 = blockIdx.x * 128;

    float numer[4][4][4], denom[4][4][4];
#pragma unroll
    for (int a = 0; a < 4; ++a)
#pragma unroll
        for (int b = 0; b < 4; ++b)
#pragma unroll
            for (int c = 0; c < 4; ++c) { numer[a][b][c] = 0.f; denom[a][b][c] = 0.f; }

    // ldmatrix lane address components (element offsets within a tile)
    const int a_row_l = lane & 15;                             // A: row within 16
    const int a_col_l = (lane >> 4) * 8;                       // A: 8-elem half within k16
    const int b_row_l = (lane & 7) + ((lane >> 4) << 3);       // B: row within 16
    const int b_col_l = ((lane >> 3) & 1) * 8;                 // B: 8-elem half within k16

    // prologue: stage 0
    load_stage_m(sbase, i0, j0, 0, t);
    asm volatile("cp.async.commit_group;");

#pragma unroll 1
    for (int kt = 0; kt < NKT; ++kt) {
        const int st = kt & 1;
        if (kt + 1 < NKT) {
            load_stage_m(sbase + (st ^ 1) * STAGEE * 2, i0, j0, (kt + 1) * KC, t);
            asm volatile("cp.async.commit_group;");
            asm volatile("cp.async.wait_group 1;");
        } else {
            asm volatile("cp.async.wait_group 0;");
        }
        __syncthreads();

        const uint32_t sb = sbase + st * STAGEE * 2;
#pragma unroll
        for (int kh = 0; kh < 2; ++kh) {
            const int kofs = kh * 16;      // elems: k16 half of the k32 chunk
            // B fragments: arrays gHi,gLo,hh; .x4 covers n16 x k16 -> two n8 frags
            uint32_t B0[2][4], B1[2][4], BH[2][4];
#pragma unroll
            for (int n2 = 0; n2 < 2; ++n2) {
                const int brow = wn * 32 + n2 * 16 + b_row_l;
                const uint32_t boff = (uint32_t)(brow * ASTRIDE + kofs + b_col_l) * 2;
                ldsm4(B0[n2], sb + 3 * TILEE * 2 + boff);
                ldsm4(B1[n2], sb + 4 * TILEE * 2 + boff);
                ldsm4(BH[n2], sb + 5 * TILEE * 2 + boff);
            }
#pragma unroll
            for (int mt = 0; mt < 4; ++mt) {
                const int arow = wm * 64 + mt * 16 + a_row_l;
                const uint32_t aoff = (uint32_t)(arow * ASTRIDE + kofs + a_col_l) * 2;
                uint32_t AH[4], AL[4], A2[4];
                ldsm4(AH, sb + 0 * TILEE * 2 + aoff);
                ldsm4(AL, sb + 1 * TILEE * 2 + aoff);
                ldsm4(A2, sb + 2 * TILEE * 2 + aoff);
#pragma unroll
                for (int n2 = 0; n2 < 2; ++n2) {
#pragma unroll
                    for (int h = 0; h < 2; ++h) {
                        const int nt = n2 * 2 + h;
                        mma_bf16(numer[mt][nt], AH, B0[n2][2 * h], B0[n2][2 * h + 1]); // sHi*gHi
                        mma_bf16(numer[mt][nt], AL, B0[n2][2 * h], B0[n2][2 * h + 1]); // sLo*gHi
                        mma_bf16(numer[mt][nt], AH, B1[n2][2 * h], B1[n2][2 * h + 1]); // sHi*gLo
                        mma_bf16(denom[mt][nt], A2, BH[n2][2 * h], BH[n2][2 * h + 1]); // s2*hh
                    }
                }
            }
        }
        __syncthreads();
    }

    // epilogue
#pragma unroll
    for (int mt = 0; mt < 4; ++mt)
#pragma unroll
        for (int nt = 0; nt < 4; ++nt) {
            const int i = i0 + wm * 64 + mt * 16 + lr;
            const int j = j0 + wn * 32 + nt * 8 + lc * 2;
            float2 v0, v1;
            v0.x = numer[mt][nt][0] * rsqrtf(denom[mt][nt][0]);
            v0.y = numer[mt][nt][1] * rsqrtf(denom[mt][nt][1]);
            v1.x = numer[mt][nt][2] * rsqrtf(denom[mt][nt][2]);
            v1.y = numer[mt][nt][3] * rsqrtf(denom[mt][nt][3]);
            *reinterpret_cast<float2*>(out + (size_t)i * BSZ + j) = v0;
            *reinterpret_cast<float2*>(out + (size_t)(i + 8) * BSZ + j) = v1;
        }
}

// ---------------- launch ----------------
extern "C" void kernel_launch(void* const* d_in, const int* in_sizes, int n_in,
                              void* d_out, int out_size) {
    (void)in_sizes; (void)n_in; (void)out_size;
    const float* img  = (const float*)d_in[0];
    const float* cap  = (const float*)d_in[1];
    // d_in[2] = lens : unused by the reference computation
    const float* Wred = (const float*)d_in[3];
    const float* bred = (const float*)d_in[4];
    const float* Wkp  = (const float*)d_in[5];
    const float* bkp  = (const float*)d_in[6];
    float* out = (float*)d_out;

    k_sum<<<BSZ, 256>>>(img);
    k_norm<<<BSZ, 256>>>(cap);
    k_repr<<<BSZ / 8, 256>>>(cap, Wred, bred);
    k_gate<<<dim3(BSZ / 128, LL / 128), 256>>>(cap, Wkp, bkp);

    cudaFuncSetAttribute(k_main, cudaFuncAttributeMaxDynamicSharedMemorySize, SMEM_MAIN);
    k_main<<<dim3(BSZ / 128, BSZ / 128), 256, SMEM_MAIN>>>(out);
}

// round 7
// speedup vs baseline: 1.3605x; 1.1042x over previous
#include <cuda_runtime.h>
#include <cuda_fp16.h>
#include <cstdint>

#define BSZ 4096
#define RR 36
#define TT 32
#define LL 1024
#define LK 256

// ---------------- scratch (__device__ globals; no allocations allowed) ----------------
__device__ __half g_sHi[BSZ * LL];   // fp16(s)
__device__ __half g_sLo[BSZ * LL];   // fp16(s - hi)
__device__ __half g_s2[BSZ * LL];    // fp16(s*s)
__device__ __half g_gg[BSZ * LL];    // fp16(gate * c_hat)
__device__ __half g_hh[BSZ * LL];    // fp16(gate*gate)
__device__ float g_repr[BSZ * LK];
__device__ float g_invn[BSZ];

// ---------------- helpers ----------------
__device__ __forceinline__ uint32_t smem_u32(const void* p) {
    uint32_t a;
    asm("{ .reg .u64 t; cvta.to.shared.u64 t, %1; cvt.u32.u64 %0, t; }" : "=r"(a) : "l"(p));
    return a;
}
__device__ __forceinline__ void cp16b(uint32_t sa, const void* g) {
    asm volatile("cp.async.cg.shared.global [%0], [%1], 16;" ::"r"(sa), "l"(g));
}
__device__ __forceinline__ void ldsm4(uint32_t r[4], uint32_t sa) {
    asm volatile("ldmatrix.sync.aligned.m8n8.x4.shared.b16 {%0,%1,%2,%3}, [%4];"
                 : "=r"(r[0]), "=r"(r[1]), "=r"(r[2]), "=r"(r[3]) : "r"(sa));
}
__device__ __forceinline__ void mma_f16(float d[4], const uint32_t a[4],
                                        uint32_t b0, uint32_t b1) {
    asm volatile(
        "mma.sync.aligned.m16n8k16.row.col.f32.f16.f16.f32 "
        "{%0,%1,%2,%3}, {%4,%5,%6,%7}, {%8,%9}, {%0,%1,%2,%3};"
        : "+f"(d[0]), "+f"(d[1]), "+f"(d[2]), "+f"(d[3])
        : "r"(a[0]), "r"(a[1]), "r"(a[2]), "r"(a[3]), "r"(b0), "r"(b1));
}

// ---------------- K1: s = img.sum(axis=1), emit fp16 splits ----------------
__global__ void k_sum(const float* __restrict__ img) {
    const int b = blockIdx.x, t = threadIdx.x;
    const float4* p = reinterpret_cast<const float4*>(img + (size_t)b * RR * LL) + t;
    float4 acc = make_float4(0.f, 0.f, 0.f, 0.f);
#pragma unroll
    for (int r = 0; r < RR; ++r) {
        float4 v = p[r * (LL / 4)];
        acc.x += v.x; acc.y += v.y; acc.z += v.z; acc.w += v.w;
    }
    const size_t o = (size_t)b * LL + t * 4;
    float s[4] = {acc.x, acc.y, acc.z, acc.w};
#pragma unroll
    for (int c = 0; c < 4; ++c) {
        __half hi = __float2half(s[c]);
        __half lo = __float2half(s[c] - __half2float(hi));
        __half s2 = __float2half(s[c] * s[c]);
        g_sHi[o + c] = hi;
        g_sLo[o + c] = lo;
        g_s2[o + c]  = s2;
    }
}

// ---------------- K2: inv_norm of cap0 rows ----------------
__global__ void k_norm(const float* __restrict__ cap) {
    const int b = blockIdx.x, t = threadIdx.x;
    const float4 v = reinterpret_cast<const float4*>(cap + (size_t)b * TT * LL)[t];
    float ss = v.x * v.x + v.y * v.y + v.z * v.z + v.w * v.w;
#pragma unroll
    for (int o = 16; o; o >>= 1) ss += __shfl_xor_sync(0xffffffffu, ss, o);
    __shared__ float red[8];
    if ((t & 31) == 0) red[t >> 5] = ss;
    __syncthreads();
    if (t == 0) {
        float tot = 0.f;
#pragma unroll
        for (int w = 0; w < 8; ++w) tot += red[w];
        g_invn[b] = rsqrtf(tot);
    }
}

// ---------------- K3: cap_repr = cap0 @ W_red^T + b_red ----------------
__global__ __launch_bounds__(256) void k_repr(const float* __restrict__ cap,
                                              const float* __restrict__ Wred,
                                              const float* __restrict__ bred) {
    __shared__ float sc[8][LL];
    const int b0 = blockIdx.x * 8, t = threadIdx.x;
#pragma unroll
    for (int bb = 0; bb < 8; ++bb)
        reinterpret_cast<float4*>(sc[bb])[t] =
            reinterpret_cast<const float4*>(cap + (size_t)(b0 + bb) * TT * LL)[t];
    __syncthreads();

    float acc[8] = {0.f, 0.f, 0.f, 0.f, 0.f, 0.f, 0.f, 0.f};
    const float4* w = reinterpret_cast<const float4*>(Wred + (size_t)t * LL);
    for (int k4 = 0; k4 < LL / 4; ++k4) {
        const float4 wv = w[k4];
#pragma unroll
        for (int bb = 0; bb < 8; ++bb) {
            const float4 cv = reinterpret_cast<const float4*>(sc[bb])[k4];
            acc[bb] += wv.x * cv.x + wv.y * cv.y + wv.z * cv.z + wv.w * cv.w;
        }
    }
    const float bias = bred[t];
#pragma unroll
    for (int bb = 0; bb < 8; ++bb)
        g_repr[(size_t)(b0 + bb) * LK + t] = acc[bb] + bias;
}

// ---------------- K4: gate GEMM (128x128 tile, 8x8/thread), fused epilogue ----------------
__device__ __forceinline__ uint32_t pkh2(__half a, __half b) {
    __half2 t = __halves2half2(a, b);
    return *reinterpret_cast<uint32_t*>(&t);
}

__global__ __launch_bounds__(256) void k_gate(const float* __restrict__ cap,
                                              const float* __restrict__ Wkp,
                                              const float* __restrict__ bkp) {
    __shared__ float Rs[16][132];
    __shared__ float Ws[16][132];
    const int t = threadIdx.x;
    const int b0 = blockIdx.x * 128;
    const int l0 = blockIdx.y * 128;
    const int tr = t >> 4, tc = t & 15;     // 16x16 thread grid, 8x8 per thread
    const int lrow = t >> 1;                // 0..127
    const int lk = (t & 1) * 8;             // 0 or 8

    float acc[8][8];
#pragma unroll
    for (int a = 0; a < 8; ++a)
#pragma unroll
        for (int b = 0; b < 8; ++b) acc[a][b] = 0.f;

    const float* gr = g_repr + (size_t)(b0 + lrow) * LK + lk;
    const float* gw = Wkp + (size_t)(l0 + lrow) * LK + lk;

    for (int kc = 0; kc < LK; kc += 16) {
        const float4 r0 = *reinterpret_cast<const float4*>(gr + kc);
        const float4 r1 = *reinterpret_cast<const float4*>(gr + kc + 4);
        const float4 w0 = *reinterpret_cast<const float4*>(gw + kc);
        const float4 w1 = *reinterpret_cast<const float4*>(gw + kc + 4);
        __syncthreads();
        Rs[lk + 0][lrow] = r0.x; Rs[lk + 1][lrow] = r0.y; Rs[lk + 2][lrow] = r0.z; Rs[lk + 3][lrow] = r0.w;
        Rs[lk + 4][lrow] = r1.x; Rs[lk + 5][lrow] = r1.y; Rs[lk + 6][lrow] = r1.z; Rs[lk + 7][lrow] = r1.w;
        Ws[lk + 0][lrow] = w0.x; Ws[lk + 1][lrow] = w0.y; Ws[lk + 2][lrow] = w0.z; Ws[lk + 3][lrow] = w0.w;
        Ws[lk + 4][lrow] = w1.x; Ws[lk + 5][lrow] = w1.y; Ws[lk + 6][lrow] = w1.z; Ws[lk + 7][lrow] = w1.w;
        __syncthreads();
#pragma unroll
        for (int k = 0; k < 16; ++k) {
            float av[8], bv[8];
            *reinterpret_cast<float4*>(av)     = *reinterpret_cast<const float4*>(&Rs[k][tr * 8]);
            *reinterpret_cast<float4*>(av + 4) = *reinterpret_cast<const float4*>(&Rs[k][tr * 8 + 4]);
            *reinterpret_cast<float4*>(bv)     = *reinterpret_cast<const float4*>(&Ws[k][tc * 8]);
            *reinterpret_cast<float4*>(bv + 4) = *reinterpret_cast<const float4*>(&Ws[k][tc * 8 + 4]);
#pragma unroll
            for (int a = 0; a < 8; ++a)
#pragma unroll
                for (int b = 0; b < 8; ++b) acc[a][b] += av[a] * bv[b];
        }
    }

    // epilogue: sigmoid + c_hat combine + fp16 emit, packed 16B stores
    float bias[8];
#pragma unroll
    for (int ci = 0; ci < 8; ++ci) bias[ci] = bkp[l0 + tc * 8 + ci];

#pragma unroll
    for (int ri = 0; ri < 8; ++ri) {
        const int b = b0 + tr * 8 + ri;
        const float inv = g_invn[b];
        const float* crow = cap + (size_t)b * TT * LL + l0 + tc * 8;
        uint32_t pg[4], ph[4];
#pragma unroll
        for (int cp = 0; cp < 4; ++cp) {
            __half gg2[2], hh2[2];
#pragma unroll
            for (int e = 0; e < 2; ++e) {
                const int ci = cp * 2 + e;
                const float z = acc[ri][ci] + bias[ci];
                const float gate = 1.0f / (1.0f + expf(-z));
                gg2[e] = __float2half(gate * crow[ci] * inv);
                hh2[e] = __float2half(gate * gate);
            }
            pg[cp] = pkh2(gg2[0], gg2[1]);
            ph[cp] = pkh2(hh2[0], hh2[1]);
        }
        const size_t o = (size_t)b * LL + l0 + tc * 8;
        *reinterpret_cast<uint4*>(g_gg + o) = make_uint4(pg[0], pg[1], pg[2], pg[3]);
        *reinterpret_cast<uint4*>(g_hh + o) = make_uint4(ph[0], ph[1], ph[2], ph[3]);
    }
}

// ---------------- K5: fused dual GEMM, ldmatrix + mma.sync (fp16, 3 products) ----------------
#define KC 32
#define ASTRIDE 40                    // fp16 elems per smem row (80B: 64 used + 16 pad)
#define TILEE (128 * ASTRIDE)         // 5120 elems per array tile
#define NARR 5                        // sHi, sLo, s2 | gg, hh
#define STAGEE (NARR * TILEE)         // 25600 elems per stage (51200 B)
#define NKT (LL / KC)                 // 32
#define SMEM_MAIN (2 * STAGEE * (int)sizeof(__half))   // 102400 B

__device__ __forceinline__ void load_stage_m(uint32_t sstage, int i0, int j0, int k0, int t) {
    const int c = t & 3;              // 16B chunk within 64B of k
    const int r = t >> 2;             // row 0..63 (also +64)
    const __half* srcs[NARR] = {g_sHi, g_sLo, g_s2, g_gg, g_hh};
#pragma unroll
    for (int a = 0; a < NARR; ++a) {
        const int base = (a < 3) ? i0 : j0;
        const __half* g = srcs[a] + (size_t)(base + r) * LL + k0 + c * 8;
        const uint32_t sa = sstage + a * TILEE * 2 + r * (ASTRIDE * 2) + c * 16;
        cp16b(sa, g);
        cp16b(sa + 64 * (ASTRIDE * 2), g + (size_t)64 * LL);
    }
}

__global__ __launch_bounds__(256, 1) void k_main(float* __restrict__ out) {
    extern __shared__ __half sm[];
    const uint32_t sbase = smem_u32(sm);
    const int t = threadIdx.x;
    const int lane = t & 31, wid = t >> 5;
    const int wm = wid >> 2, wn = wid & 3;     // 2x4 warp grid, warp tile 64x32
    const int lr = lane >> 2, lc = lane & 3;
    const int i0 = blockIdx.y * 128, j0 = blockIdx.x * 128;

    float numer[4][4][4], denom[4][4][4];
#pragma unroll
    for (int a = 0; a < 4; ++a)
#pragma unroll
        for (int b = 0; b < 4; ++b)
#pragma unroll
            for (int c = 0; c < 4; ++c) { numer[a][b][c] = 0.f; denom[a][b][c] = 0.f; }

    // ldmatrix lane address components (element offsets within a tile)
    const int a_row_l = lane & 15;                             // A: row within 16
    const int a_col_l = (lane >> 4) * 8;                       // A: 8-elem half within k16
    const int b_row_l = (lane & 7) + ((lane >> 4) << 3);       // B: row within 16
    const int b_col_l = ((lane >> 3) & 1) * 8;                 // B: 8-elem half within k16

    // prologue: stage 0
    load_stage_m(sbase, i0, j0, 0, t);
    asm volatile("cp.async.commit_group;");

#pragma unroll 1
    for (int kt = 0; kt < NKT; ++kt) {
        const int st = kt & 1;
        if (kt + 1 < NKT) {
            load_stage_m(sbase + (st ^ 1) * STAGEE * 2, i0, j0, (kt + 1) * KC, t);
            asm volatile("cp.async.commit_group;");
            asm volatile("cp.async.wait_group 1;");
        } else {
            asm volatile("cp.async.wait_group 0;");
        }
        __syncthreads();

        const uint32_t sb = sbase + st * STAGEE * 2;
#pragma unroll
        for (int kh = 0; kh < 2; ++kh) {
            const int kofs = kh * 16;      // elems: k16 half of the k32 chunk
            // B fragments: arrays gg, hh; .x4 covers n16 x k16 -> two n8 frags
            uint32_t BG[2][4], BH[2][4];
#pragma unroll
            for (int n2 = 0; n2 < 2; ++n2) {
                const int brow = wn * 32 + n2 * 16 + b_row_l;
                const uint32_t boff = (uint32_t)(brow * ASTRIDE + kofs + b_col_l) * 2;
                ldsm4(BG[n2], sb + 3 * TILEE * 2 + boff);
                ldsm4(BH[n2], sb + 4 * TILEE * 2 + boff);
            }
#pragma unroll
            for (int mt = 0; mt < 4; ++mt) {
                const int arow = wm * 64 + mt * 16 + a_row_l;
                const uint32_t aoff = (uint32_t)(arow * ASTRIDE + kofs + a_col_l) * 2;
                uint32_t AH[4], AL[4], A2[4];
                ldsm4(AH, sb + 0 * TILEE * 2 + aoff);
                ldsm4(AL, sb + 1 * TILEE * 2 + aoff);
                ldsm4(A2, sb + 2 * TILEE * 2 + aoff);
#pragma unroll
                for (int n2 = 0; n2 < 2; ++n2) {
#pragma unroll
                    for (int h = 0; h < 2; ++h) {
                        const int nt = n2 * 2 + h;
                        mma_f16(numer[mt][nt], AH, BG[n2][2 * h], BG[n2][2 * h + 1]); // sHi*g
                        mma_f16(numer[mt][nt], AL, BG[n2][2 * h], BG[n2][2 * h + 1]); // sLo*g
                        mma_f16(denom[mt][nt], A2, BH[n2][2 * h], BH[n2][2 * h + 1]); // s2*h
                    }
                }
            }
        }
        __syncthreads();
    }

    // epilogue
#pragma unroll
    for (int mt = 0; mt < 4; ++mt)
#pragma unroll
        for (int nt = 0; nt < 4; ++nt) {
            const int i = i0 + wm * 64 + mt * 16 + lr;
            const int j = j0 + wn * 32 + nt * 8 + lc * 2;
            float2 v0, v1;
            v0.x = numer[mt][nt][0] * rsqrtf(denom[mt][nt][0]);
            v0.y = numer[mt][nt][1] * rsqrtf(denom[mt][nt][1]);
            v1.x = numer[mt][nt][2] * rsqrtf(denom[mt][nt][2]);
            v1.y = numer[mt][nt][3] * rsqrtf(denom[mt][nt][3]);
            *reinterpret_cast<float2*>(out + (size_t)i * BSZ + j) = v0;
            *reinterpret_cast<float2*>(out + (size_t)(i + 8) * BSZ + j) = v1;
        }
}

// ---------------- launch ----------------
extern "C" void kernel_launch(void* const* d_in, const int* in_sizes, int n_in,
                              void* d_out, int out_size) {
    (void)in_sizes; (void)n_in; (void)out_size;
    const float* img  = (const float*)d_in[0];
    const float* cap  = (const float*)d_in[1];
    // d_in[2] = lens : unused by the reference computation
    const float* Wred = (const float*)d_in[3];
    const float* bred = (const float*)d_in[4];
    const float* Wkp  = (const float*)d_in[5];
    const float* bkp  = (const float*)d_in[6];
    float* out = (float*)d_out;

    k_sum<<<BSZ, 256>>>(img);
    k_norm<<<BSZ, 256>>>(cap);
    k_repr<<<BSZ / 8, 256>>>(cap, Wred, bred);
    k_gate<<<dim3(BSZ / 128, LL / 128), 256>>>(cap, Wkp, bkp);

    cudaFuncSetAttribute(k_main, cudaFuncAttributeMaxDynamicSharedMemorySize, SMEM_MAIN);
    k_main<<<dim3(BSZ / 128, BSZ / 128), 256, SMEM_MAIN>>>(out);
}

// round 8
// speedup vs baseline: 1.3639x; 1.0026x over previous
#include <cuda_runtime.h>
#include <cuda_fp16.h>
#include <cstdint>

#define BSZ 4096
#define RR 36
#define TT 32
#define LL 1024
#define LK 256

// ---------------- scratch (__device__ globals; no allocations allowed) ----------------
__device__ __half g_sHi[BSZ * LL];   // fp16(s)
__device__ __half g_sLo[BSZ * LL];   // fp16(s - hi)
__device__ __half g_s2[BSZ * LL];    // fp16(s*s)
__device__ __half g_gg[BSZ * LL];    // fp16(gate * c_hat)
__device__ __half g_hh[BSZ * LL];    // fp16(gate*gate)
__device__ float g_repr[BSZ * LK];
__device__ float g_invn[BSZ];

// ---------------- helpers ----------------
__device__ __forceinline__ uint32_t smem_u32(const void* p) {
    uint32_t a;
    asm("{ .reg .u64 t; cvta.to.shared.u64 t, %1; cvt.u32.u64 %0, t; }" : "=r"(a) : "l"(p));
    return a;
}
__device__ __forceinline__ void cp16b(uint32_t sa, const void* g) {
    asm volatile("cp.async.cg.shared.global [%0], [%1], 16;" ::"r"(sa), "l"(g));
}
__device__ __forceinline__ void ldsm4(uint32_t r[4], uint32_t sa) {
    asm volatile("ldmatrix.sync.aligned.m8n8.x4.shared.b16 {%0,%1,%2,%3}, [%4];"
                 : "=r"(r[0]), "=r"(r[1]), "=r"(r[2]), "=r"(r[3]) : "r"(sa));
}
// NOTE: non-volatile — pure register computation, lets ptxas schedule/pipeline MMAs.
__device__ __forceinline__ void mma_f16(float d[4], const uint32_t a[4],
                                        uint32_t b0, uint32_t b1) {
    asm("mma.sync.aligned.m16n8k16.row.col.f32.f16.f16.f32 "
        "{%0,%1,%2,%3}, {%4,%5,%6,%7}, {%8,%9}, {%0,%1,%2,%3};"
        : "+f"(d[0]), "+f"(d[1]), "+f"(d[2]), "+f"(d[3])
        : "r"(a[0]), "r"(a[1]), "r"(a[2]), "r"(a[3]), "r"(b0), "r"(b1));
}

// ---------------- K1: s = img.sum(axis=1), emit fp16 splits ----------------
__global__ void k_sum(const float* __restrict__ img) {
    const int b = blockIdx.x, t = threadIdx.x;
    const float4* p = reinterpret_cast<const float4*>(img + (size_t)b * RR * LL) + t;
    float4 acc = make_float4(0.f, 0.f, 0.f, 0.f);
#pragma unroll
    for (int r = 0; r < RR; ++r) {
        float4 v = p[r * (LL / 4)];
        acc.x += v.x; acc.y += v.y; acc.z += v.z; acc.w += v.w;
    }
    const size_t o = (size_t)b * LL + t * 4;
    float s[4] = {acc.x, acc.y, acc.z, acc.w};
#pragma unroll
    for (int c = 0; c < 4; ++c) {
        __half hi = __float2half(s[c]);
        __half lo = __float2half(s[c] - __half2float(hi));
        __half s2 = __float2half(s[c] * s[c]);
        g_sHi[o + c] = hi;
        g_sLo[o + c] = lo;
        g_s2[o + c]  = s2;
    }
}

// ---------------- K2: inv_norm of cap0 rows ----------------
__global__ void k_norm(const float* __restrict__ cap) {
    const int b = blockIdx.x, t = threadIdx.x;
    const float4 v = reinterpret_cast<const float4*>(cap + (size_t)b * TT * LL)[t];
    float ss = v.x * v.x + v.y * v.y + v.z * v.z + v.w * v.w;
#pragma unroll
    for (int o = 16; o; o >>= 1) ss += __shfl_xor_sync(0xffffffffu, ss, o);
    __shared__ float red[8];
    if ((t & 31) == 0) red[t >> 5] = ss;
    __syncthreads();
    if (t == 0) {
        float tot = 0.f;
#pragma unroll
        for (int w = 0; w < 8; ++w) tot += red[w];
        g_invn[b] = rsqrtf(tot);
    }
}

// ---------------- K3: cap_repr = cap0 @ W_red^T + b_red ----------------
__global__ __launch_bounds__(256) void k_repr(const float* __restrict__ cap,
                                              const float* __restrict__ Wred,
                                              const float* __restrict__ bred) {
    __shared__ float sc[8][LL];
    const int b0 = blockIdx.x * 8, t = threadIdx.x;
#pragma unroll
    for (int bb = 0; bb < 8; ++bb)
        reinterpret_cast<float4*>(sc[bb])[t] =
            reinterpret_cast<const float4*>(cap + (size_t)(b0 + bb) * TT * LL)[t];
    __syncthreads();

    float acc[8] = {0.f, 0.f, 0.f, 0.f, 0.f, 0.f, 0.f, 0.f};
    const float4* w = reinterpret_cast<const float4*>(Wred + (size_t)t * LL);
    for (int k4 = 0; k4 < LL / 4; ++k4) {
        const float4 wv = w[k4];
#pragma unroll
        for (int bb = 0; bb < 8; ++bb) {
            const float4 cv = reinterpret_cast<const float4*>(sc[bb])[k4];
            acc[bb] += wv.x * cv.x + wv.y * cv.y + wv.z * cv.z + wv.w * cv.w;
        }
    }
    const float bias = bred[t];
#pragma unroll
    for (int bb = 0; bb < 8; ++bb)
        g_repr[(size_t)(b0 + bb) * LK + t] = acc[bb] + bias;
}

// ---------------- K4: gate GEMM (128x128 tile, 8x8/thread), fused epilogue ----------------
__device__ __forceinline__ uint32_t pkh2(__half a, __half b) {
    __half2 t = __halves2half2(a, b);
    return *reinterpret_cast<uint32_t*>(&t);
}

__global__ __launch_bounds__(256) void k_gate(const float* __restrict__ cap,
                                              const float* __restrict__ Wkp,
                                              const float* __restrict__ bkp) {
    __shared__ float Rs[16][132];
    __shared__ float Ws[16][132];
    const int t = threadIdx.x;
    const int b0 = blockIdx.x * 128;
    const int l0 = blockIdx.y * 128;
    const int tr = t >> 4, tc = t & 15;     // 16x16 thread grid, 8x8 per thread
    const int lrow = t >> 1;                // 0..127
    const int lk = (t & 1) * 8;             // 0 or 8

    float acc[8][8];
#pragma unroll
    for (int a = 0; a < 8; ++a)
#pragma unroll
        for (int b = 0; b < 8; ++b) acc[a][b] = 0.f;

    const float* gr = g_repr + (size_t)(b0 + lrow) * LK + lk;
    const float* gw = Wkp + (size_t)(l0 + lrow) * LK + lk;

    for (int kc = 0; kc < LK; kc += 16) {
        const float4 r0 = *reinterpret_cast<const float4*>(gr + kc);
        const float4 r1 = *reinterpret_cast<const float4*>(gr + kc + 4);
        const float4 w0 = *reinterpret_cast<const float4*>(gw + kc);
        const float4 w1 = *reinterpret_cast<const float4*>(gw + kc + 4);
        __syncthreads();
        Rs[lk + 0][lrow] = r0.x; Rs[lk + 1][lrow] = r0.y; Rs[lk + 2][lrow] = r0.z; Rs[lk + 3][lrow] = r0.w;
        Rs[lk + 4][lrow] = r1.x; Rs[lk + 5][lrow] = r1.y; Rs[lk + 6][lrow] = r1.z; Rs[lk + 7][lrow] = r1.w;
        Ws[lk + 0][lrow] = w0.x; Ws[lk + 1][lrow] = w0.y; Ws[lk + 2][lrow] = w0.z; Ws[lk + 3][lrow] = w0.w;
        Ws[lk + 4][lrow] = w1.x; Ws[lk + 5][lrow] = w1.y; Ws[lk + 6][lrow] = w1.z; Ws[lk + 7][lrow] = w1.w;
        __syncthreads();
#pragma unroll
        for (int k = 0; k < 16; ++k) {
            float av[8], bv[8];
            *reinterpret_cast<float4*>(av)     = *reinterpret_cast<const float4*>(&Rs[k][tr * 8]);
            *reinterpret_cast<float4*>(av + 4) = *reinterpret_cast<const float4*>(&Rs[k][tr * 8 + 4]);
            *reinterpret_cast<float4*>(bv)     = *reinterpret_cast<const float4*>(&Ws[k][tc * 8]);
            *reinterpret_cast<float4*>(bv + 4) = *reinterpret_cast<const float4*>(&Ws[k][tc * 8 + 4]);
#pragma unroll
            for (int a = 0; a < 8; ++a)
#pragma unroll
                for (int b = 0; b < 8; ++b) acc[a][b] += av[a] * bv[b];
        }
    }

    // epilogue: sigmoid + c_hat combine + fp16 emit, packed 16B stores
    float bias[8];
#pragma unroll
    for (int ci = 0; ci < 8; ++ci) bias[ci] = bkp[l0 + tc * 8 + ci];

#pragma unroll
    for (int ri = 0; ri < 8; ++ri) {
        const int b = b0 + tr * 8 + ri;
        const float inv = g_invn[b];
        const float* crow = cap + (size_t)b * TT * LL + l0 + tc * 8;
        uint32_t pg[4], ph[4];
#pragma unroll
        for (int cp = 0; cp < 4; ++cp) {
            __half gg2[2], hh2[2];
#pragma unroll
            for (int e = 0; e < 2; ++e) {
                const int ci = cp * 2 + e;
                const float z = acc[ri][ci] + bias[ci];
                const float gate = 1.0f / (1.0f + expf(-z));
                gg2[e] = __float2half(gate * crow[ci] * inv);
                hh2[e] = __float2half(gate * gate);
            }
            pg[cp] = pkh2(gg2[0], gg2[1]);
            ph[cp] = pkh2(hh2[0], hh2[1]);
        }
        const size_t o = (size_t)b * LL + l0 + tc * 8;
        *reinterpret_cast<uint4*>(g_gg + o) = make_uint4(pg[0], pg[1], pg[2], pg[3]);
        *reinterpret_cast<uint4*>(g_hh + o) = make_uint4(ph[0], ph[1], ph[2], ph[3]);
    }
}

// ---------------- K5: fused dual GEMM, ldmatrix + mma.sync (fp16, 3 products) ----------------
#define KC 32
#define ASTRIDE 40                    // fp16 elems per smem row (80B: 64 used + 16 pad)
#define TILEE (128 * ASTRIDE)         // 5120 elems per array tile
#define NARR 5                        // sHi, sLo, s2 | gg, hh
#define STAGEE (NARR * TILEE)         // 25600 elems per stage (51200 B)
#define NKT (LL / KC)                 // 32
#define SMEM_MAIN (2 * STAGEE * (int)sizeof(__half))   // 102400 B

__device__ __forceinline__ void load_stage_m(uint32_t sstage, int i0, int j0, int k0, int t) {
    const int c = t & 3;              // 16B chunk within 64B of k
    const int r = t >> 2;             // row 0..63 (also +64)
    const __half* srcs[NARR] = {g_sHi, g_sLo, g_s2, g_gg, g_hh};
#pragma unroll
    for (int a = 0; a < NARR; ++a) {
        const int base = (a < 3) ? i0 : j0;
        const __half* g = srcs[a] + (size_t)(base + r) * LL + k0 + c * 8;
        const uint32_t sa = sstage + a * TILEE * 2 + r * (ASTRIDE * 2) + c * 16;
        cp16b(sa, g);
        cp16b(sa + 64 * (ASTRIDE * 2), g + (size_t)64 * LL);
    }
}

__global__ __launch_bounds__(256, 1) void k_main(float* __restrict__ out) {
    extern __shared__ __half sm[];
    const uint32_t sbase = smem_u32(sm);
    const int t = threadIdx.x;
    const int lane = t & 31, wid = t >> 5;
    const int wm = wid >> 2, wn = wid & 3;     // 2x4 warp grid, warp tile 64x32
    const int lr = lane >> 2, lc = lane & 3;
    const int i0 = blockIdx.y * 128, j0 = blockIdx.x * 128;

    float numer[4][4][4], denom[4][4][4];
#pragma unroll
    for (int a = 0; a < 4; ++a)
#pragma unroll
        for (int b = 0; b < 4; ++b)
#pragma unroll
            for (int c = 0; c < 4; ++c) { numer[a][b][c] = 0.f; denom[a][b][c] = 0.f; }

    // ldmatrix lane address components (element offsets within a tile)
    const int a_row_l = lane & 15;                             // A: row within 16
    const int a_col_l = (lane >> 4) * 8;                       // A: 8-elem half within k16
    const int b_row_l = (lane & 7) + ((lane >> 4) << 3);       // B: row within 16
    const int b_col_l = ((lane >> 3) & 1) * 8;                 // B: 8-elem half within k16

    // prologue: stage 0
    load_stage_m(sbase, i0, j0, 0, t);
    asm volatile("cp.async.commit_group;");

#pragma unroll 1
    for (int kt = 0; kt < NKT; ++kt) {
        const int st = kt & 1;
        if (kt + 1 < NKT) {
            load_stage_m(sbase + (st ^ 1) * STAGEE * 2, i0, j0, (kt + 1) * KC, t);
            asm volatile("cp.async.commit_group;");
            asm volatile("cp.async.wait_group 1;");
        } else {
            asm volatile("cp.async.wait_group 0;");
        }
        __syncthreads();

        const uint32_t sb = sbase + st * STAGEE * 2;
#pragma unroll
        for (int kh = 0; kh < 2; ++kh) {
            const int kofs = kh * 16;      // elems: k16 half of the k32 chunk
            // B fragments: arrays gg, hh; .x4 covers n16 x k16 -> two n8 frags
            uint32_t BG[2][4], BH[2][4];
#pragma unroll
            for (int n2 = 0; n2 < 2; ++n2) {
                const int brow = wn * 32 + n2 * 16 + b_row_l;
                const uint32_t boff = (uint32_t)(brow * ASTRIDE + kofs + b_col_l) * 2;
                ldsm4(BG[n2], sb + 3 * TILEE * 2 + boff);
                ldsm4(BH[n2], sb + 4 * TILEE * 2 + boff);
            }
#pragma unroll
            for (int mt = 0; mt < 4; ++mt) {
                const int arow = wm * 64 + mt * 16 + a_row_l;
                const uint32_t aoff = (uint32_t)(arow * ASTRIDE + kofs + a_col_l) * 2;
                uint32_t AH[4], AL[4], A2[4];
                ldsm4(AH, sb + 0 * TILEE * 2 + aoff);
                ldsm4(AL, sb + 1 * TILEE * 2 + aoff);
                ldsm4(A2, sb + 2 * TILEE * 2 + aoff);
                // product-major order: same accumulator re-touched only after 4
                // independent MMAs -> covers HMMA latency, no RAW bubble
#pragma unroll
                for (int nt = 0; nt < 4; ++nt)
                    mma_f16(numer[mt][nt], AH, BG[nt >> 1][2 * (nt & 1)], BG[nt >> 1][2 * (nt & 1) + 1]);
#pragma unroll
                for (int nt = 0; nt < 4; ++nt)
                    mma_f16(numer[mt][nt], AL, BG[nt >> 1][2 * (nt & 1)], BG[nt >> 1][2 * (nt & 1) + 1]);
#pragma unroll
                for (int nt = 0; nt < 4; ++nt)
                    mma_f16(denom[mt][nt], A2, BH[nt >> 1][2 * (nt & 1)], BH[nt >> 1][2 * (nt & 1) + 1]);
            }
        }
        __syncthreads();
    }

    // epilogue
#pragma unroll
    for (int mt = 0; mt < 4; ++mt)
#pragma unroll
        for (int nt = 0; nt < 4; ++nt) {
            const int i = i0 + wm * 64 + mt * 16 + lr;
            const int j = j0 + wn * 32 + nt * 8 + lc * 2;
            float2 v0, v1;
            v0.x = numer[mt][nt][0] * rsqrtf(denom[mt][nt][0]);
            v0.y = numer[mt][nt][1] * rsqrtf(denom[mt][nt][1]);
            v1.x = numer[mt][nt][2] * rsqrtf(denom[mt][nt][2]);
            v1.y = numer[mt][nt][3] * rsqrtf(denom[mt][nt][3]);
            *reinterpret_cast<float2*>(out + (size_t)i * BSZ + j) = v0;
            *reinterpret_cast<float2*>(out + (size_t)(i + 8) * BSZ + j) = v1;
        }
}

// ---------------- launch ----------------
extern "C" void kernel_launch(void* const* d_in, const int* in_sizes, int n_in,
                              void* d_out, int out_size) {
    (void)in_sizes; (void)n_in; (void)out_size;
    const float* img  = (const float*)d_in[0];
    const float* cap  = (const float*)d_in[1];
    // d_in[2] = lens : unused by the reference computation
    const float* Wred = (const float*)d_in[3];
    const float* bred = (const float*)d_in[4];
    const float* Wkp  = (const float*)d_in[5];
    const float* bkp  = (const float*)d_in[6];
    float* out = (float*)d_out;

    k_sum<<<BSZ, 256>>>(img);
    k_norm<<<BSZ, 256>>>(cap);
    k_repr<<<BSZ / 8, 256>>>(cap, Wred, bred);
    k_gate<<<dim3(BSZ / 128, LL / 128), 256>>>(cap, Wkp, bkp);

    cudaFuncSetAttribute(k_main, cudaFuncAttributeMaxDynamicSharedMemorySize, SMEM_MAIN);
    k_main<<<dim3(BSZ / 128, BSZ / 128), 256, SMEM_MAIN>>>(out);
}

// round 11
// speedup vs baseline: 1.5379x; 1.1276x over previous
#include <cuda_runtime.h>
#include <cuda_fp16.h>
#include <cstdint>

#define BSZ 4096
#define RR 36
#define TT 32
#define LL 1024
#define LK 256

// ---------------- scratch (__device__ globals; no allocations allowed) ----------------
__device__ __half g_sHi[BSZ * LL];   // fp16(s)
__device__ __half g_sLo[BSZ * LL];   // fp16(s - hi)
__device__ __half g_s2[BSZ * LL];    // fp16(s*s)
__device__ __half g_gg[BSZ * LL];    // fp16(gate * c_hat)
__device__ __half g_hh[BSZ * LL];    // fp16(gate*gate)
__device__ __half g_rHi[BSZ * LK];   // fp16(cap_repr)
__device__ __half g_rLo[BSZ * LK];   // fp16(residual)
__device__ __half g_wH[LL * LK];     // fp16(W_kp)
__device__ float g_invn[BSZ];

// ---------------- helpers ----------------
__device__ __forceinline__ uint32_t smem_u32(const void* p) {
    uint32_t a;
    asm("{ .reg .u64 t; cvta.to.shared.u64 t, %1; cvt.u32.u64 %0, t; }" : "=r"(a) : "l"(p));
    return a;
}
__device__ __forceinline__ void cp16b(uint32_t sa, const void* g) {
    asm volatile("cp.async.cg.shared.global [%0], [%1], 16;" ::"r"(sa), "l"(g));
}
__device__ __forceinline__ void ldsm4(uint32_t r[4], uint32_t sa) {
    asm volatile("ldmatrix.sync.aligned.m8n8.x4.shared.b16 {%0,%1,%2,%3}, [%4];"
                 : "=r"(r[0]), "=r"(r[1]), "=r"(r[2]), "=r"(r[3]) : "r"(sa));
}
__device__ __forceinline__ void mma_f16(float d[4], const uint32_t a[4],
                                        uint32_t b0, uint32_t b1) {
    asm("mma.sync.aligned.m16n8k16.row.col.f32.f16.f16.f32 "
        "{%0,%1,%2,%3}, {%4,%5,%6,%7}, {%8,%9}, {%0,%1,%2,%3};"
        : "+f"(d[0]), "+f"(d[1]), "+f"(d[2]), "+f"(d[3])
        : "r"(a[0]), "r"(a[1]), "r"(a[2]), "r"(a[3]), "r"(b0), "r"(b1));
}

// ---------------- K1: s = img.sum(axis=1), emit fp16 splits ----------------
__global__ void k_sum(const float* __restrict__ img) {
    const int b = blockIdx.x, t = threadIdx.x;
    const float4* p = reinterpret_cast<const float4*>(img + (size_t)b * RR * LL) + t;
    float4 acc = make_float4(0.f, 0.f, 0.f, 0.f);
#pragma unroll
    for (int r = 0; r < RR; ++r) {
        float4 v = p[r * (LL / 4)];
        acc.x += v.x; acc.y += v.y; acc.z += v.z; acc.w += v.w;
    }
    const size_t o = (size_t)b * LL + t * 4;
    float s[4] = {acc.x, acc.y, acc.z, acc.w};
#pragma unroll
    for (int c = 0; c < 4; ++c) {
        __half hi = __float2half(s[c]);
        __half lo = __float2half(s[c] - __half2float(hi));
        __half s2 = __float2half(s[c] * s[c]);
        g_sHi[o + c] = hi;
        g_sLo[o + c] = lo;
        g_s2[o + c]  = s2;
    }
}

// ---------------- K2: inv_norm of cap0 rows ----------------
__global__ void k_norm(const float* __restrict__ cap) {
    const int b = blockIdx.x, t = threadIdx.x;
    const float4 v = reinterpret_cast<const float4*>(cap + (size_t)b * TT * LL)[t];
    float ss = v.x * v.x + v.y * v.y + v.z * v.z + v.w * v.w;
#pragma unroll
    for (int o = 16; o; o >>= 1) ss += __shfl_xor_sync(0xffffffffu, ss, o);
    __shared__ float red[8];
    if ((t & 31) == 0) red[t >> 5] = ss;
    __syncthreads();
    if (t == 0) {
        float tot = 0.f;
#pragma unroll
        for (int w = 0; w < 8; ++w) tot += red[w];
        g_invn[b] = rsqrtf(tot);
    }
}

// ---------------- K3: cap_repr = cap0 @ W_red^T + b_red (emit fp16 splits) ----------------
__global__ __launch_bounds__(256) void k_repr(const float* __restrict__ cap,
                                              const float* __restrict__ Wred,
                                              const float* __restrict__ bred) {
    __shared__ float sc[8][LL];
    const int b0 = blockIdx.x * 8, t = threadIdx.x;
#pragma unroll
    for (int bb = 0; bb < 8; ++bb)
        reinterpret_cast<float4*>(sc[bb])[t] =
            reinterpret_cast<const float4*>(cap + (size_t)(b0 + bb) * TT * LL)[t];
    __syncthreads();

    float acc[8] = {0.f, 0.f, 0.f, 0.f, 0.f, 0.f, 0.f, 0.f};
    const float4* w = reinterpret_cast<const float4*>(Wred + (size_t)t * LL);
    for (int k4 = 0; k4 < LL / 4; ++k4) {
        const float4 wv = w[k4];
#pragma unroll
        for (int bb = 0; bb < 8; ++bb) {
            const float4 cv = reinterpret_cast<const float4*>(sc[bb])[k4];
            acc[bb] += wv.x * cv.x + wv.y * cv.y + wv.z * cv.z + wv.w * cv.w;
        }
    }
    const float bias = bred[t];
#pragma unroll
    for (int bb = 0; bb < 8; ++bb) {
        const float v = acc[bb] + bias;
        const __half hi = __float2half(v);
        const __half lo = __float2half(v - __half2float(hi));
        g_rHi[(size_t)(b0 + bb) * LK + t] = hi;
        g_rLo[(size_t)(b0 + bb) * LK + t] = lo;
    }
}

// ---------------- K3b: Wkp -> fp16 ----------------
__global__ void k_wsplit(const float* __restrict__ Wkp) {
    const int i = blockIdx.x * 256 + threadIdx.x;     // float4 index
    const float4 v = reinterpret_cast<const float4*>(Wkp)[i];
    __half2 h0 = __floats2half2_rn(v.x, v.y);
    __half2 h1 = __floats2half2_rn(v.z, v.w);
    uint2 pk;
    pk.x = *reinterpret_cast<uint32_t*>(&h0);
    pk.y = *reinterpret_cast<uint32_t*>(&h1);
    *reinterpret_cast<uint2*>(g_wH + (size_t)i * 4) = pk;
}

// ---------------- K4: gate via split-fp16 HMMA; fused sigmoid epilogue ----------------
// z[b,l] = (rHi+rLo)[b,:] . wH[l,:],  K=256
#define GKC 64
#define GSTR 72                       // fp16 elems per smem row (144B) — conflict-free LDSM
#define GTILE (128 * GSTR)            // elems
#define GTILE_B (GTILE * 2)           // bytes
#define GNARR 3                       // rHi, rLo | wH
#define GSTAGE_B (GNARR * GTILE_B)    // 55296 B
#define GNKT (LK / GKC)               // 4
#define SMEM_GATE (2 * GSTAGE_B)      // 110592 B

__device__ __forceinline__ void load_stage_g(uint32_t sstage, int i0, int j0, int k0, int t) {
    const int c = t & 7;              // 16B chunk within 128B of k
    const int r0 = t >> 3;            // 0..31
    const __half* srcs[GNARR] = {g_rHi, g_rLo, g_wH};
#pragma unroll
    for (int a = 0; a < GNARR; ++a) {
        const int base = (a < 2) ? i0 : j0;
        const __half* g = srcs[a] + (size_t)(base + r0) * LK + k0 + c * 8;
        const uint32_t sa = sstage + a * GTILE_B + r0 * (GSTR * 2) + c * 16;
#pragma unroll
        for (int e = 0; e < 4; ++e)
            cp16b(sa + e * 32 * (GSTR * 2), g + (size_t)e * 32 * LK);
    }
}

__global__ __launch_bounds__(256, 1) void k_gate(const float* __restrict__ cap,
                                                 const float* __restrict__ bkp) {
    extern __shared__ __half smg[];
    const uint32_t sbase = smem_u32(smg);
    const int t = threadIdx.x;
    const int lane = t & 31, wid = t >> 5;
    const int wm = wid >> 2, wn = wid & 3;     // 2x4 warp grid, warp tile 64x32
    const int lr = lane >> 2, lc = lane & 3;
    const int i0 = blockIdx.y * 128;           // batch
    const int j0 = blockIdx.x * 128;           // l feature

    float z[4][4][4];
#pragma unroll
    for (int a = 0; a < 4; ++a)
#pragma unroll
        for (int b = 0; b < 4; ++b)
#pragma unroll
            for (int c = 0; c < 4; ++c) z[a][b][c] = 0.f;

    const int a_row_l = lane & 15;
    const int a_col_l = (lane >> 4) * 8;
    const int b_row_l = (lane & 7) + ((lane >> 4) << 3);
    const int b_col_l = ((lane >> 3) & 1) * 8;

    load_stage_g(sbase, i0, j0, 0, t);
    asm volatile("cp.async.commit_group;");

#pragma unroll 1
    for (int kt = 0; kt < GNKT; ++kt) {
        const int st = kt & 1;
        if (kt + 1 < GNKT) {
            load_stage_g(sbase + (st ^ 1) * GSTAGE_B, i0, j0, (kt + 1) * GKC, t);
            asm volatile("cp.async.commit_group;");
            asm volatile("cp.async.wait_group 1;");
        } else {
            asm volatile("cp.async.wait_group 0;");
        }
        __syncthreads();
        const uint32_t sb = sbase + st * GSTAGE_B;
#pragma unroll
        for (int kh = 0; kh < 4; ++kh) {
            const int kofs = kh * 16;
            uint32_t BW[2][4];
#pragma unroll
            for (int n2 = 0; n2 < 2; ++n2) {
                const int brow = wn * 32 + n2 * 16 + b_row_l;
                ldsm4(BW[n2], sb + 2 * GTILE_B + (uint32_t)(brow * GSTR + kofs + b_col_l) * 2);
            }
            uint32_t A[2][2][4];   // [buf][hi/lo][frag]
            {
                const int arow = wm * 64 + a_row_l;
                const uint32_t ao = (uint32_t)(arow * GSTR + kofs + a_col_l) * 2;
                ldsm4(A[0][0], sb + 0 * GTILE_B + ao);
                ldsm4(A[0][1], sb + 1 * GTILE_B + ao);
            }
#pragma unroll
            for (int mt = 0; mt < 4; ++mt) {
                if (mt < 3) {
                    const int arow = wm * 64 + (mt + 1) * 16 + a_row_l;
                    const uint32_t ao = (uint32_t)(arow * GSTR + kofs + a_col_l) * 2;
                    ldsm4(A[(mt + 1) & 1][0], sb + 0 * GTILE_B + ao);
                    ldsm4(A[(mt + 1) & 1][1], sb + 1 * GTILE_B + ao);
                }
#pragma unroll
                for (int nt = 0; nt < 4; ++nt)
                    mma_f16(z[mt][nt], A[mt & 1][0], BW[nt >> 1][2 * (nt & 1)], BW[nt >> 1][2 * (nt & 1) + 1]);
#pragma unroll
                for (int nt = 0; nt < 4; ++nt)
                    mma_f16(z[mt][nt], A[mt & 1][1], BW[nt >> 1][2 * (nt & 1)], BW[nt >> 1][2 * (nt & 1) + 1]);
            }
        }
        __syncthreads();
    }

    // epilogue: sigmoid + combine with c_hat; emit gg, hh (fp16)
#pragma unroll
    for (int mt = 0; mt < 4; ++mt)
#pragma unroll
        for (int nt = 0; nt < 4; ++nt) {
            const int j = j0 + wn * 32 + nt * 8 + lc * 2;
            const float2 bb = *reinterpret_cast<const float2*>(bkp + j);
#pragma unroll
            for (int h = 0; h < 2; ++h) {
                const int i = i0 + wm * 64 + mt * 16 + lr + h * 8;
                const float inv = g_invn[i];
                const float2 cv = *reinterpret_cast<const float2*>(cap + (size_t)i * TT * LL + j);
                const float z0 = z[mt][nt][2 * h + 0] + bb.x;
                const float z1 = z[mt][nt][2 * h + 1] + bb.y;
                const float gt0 = 1.0f / (1.0f + expf(-z0));
                const float gt1 = 1.0f / (1.0f + expf(-z1));
                __half2 gg = __floats2half2_rn(gt0 * cv.x * inv, gt1 * cv.y * inv);
                __half2 hh = __floats2half2_rn(gt0 * gt0, gt1 * gt1);
                *reinterpret_cast<__half2*>(g_gg + (size_t)i * LL + j) = gg;
                *reinterpret_cast<__half2*>(g_hh + (size_t)i * LL + j) = hh;
            }
        }
}

// ---------------- K5: fused dual GEMM, ldmatrix + mma.sync (fp16, 3 products) ----------------
#define KC 64
#define ASTRIDE 72                    // fp16 elems per smem row (144B) — conflict-free LDSM
#define TILEE (128 * ASTRIDE)         // 9216 elems per array tile
#define TILE_B (TILEE * 2)            // 18432 bytes
#define NARR 5                        // sHi, sLo, s2 | gg, hh
#define STAGE_B (NARR * TILE_B)       // 92160 B per stage
#define NKT (LL / KC)                 // 16
#define SMEM_MAIN (2 * STAGE_B)       // 184320 B

__device__ __forceinline__ void load_stage_m(uint32_t sstage, int i0, int j0, int k0, int t) {
    const int c = t & 7;              // 16B chunk within 128B of k
    const int r0 = t >> 3;            // 0..31
    const __half* srcs[NARR] = {g_sHi, g_sLo, g_s2, g_gg, g_hh};
#pragma unroll
    for (int a = 0; a < NARR; ++a) {
        const int base = (a < 3) ? i0 : j0;
        const __half* g = srcs[a] + (size_t)(base + r0) * LL + k0 + c * 8;
        const uint32_t sa = sstage + a * TILE_B + r0 * (ASTRIDE * 2) + c * 16;
#pragma unroll
        for (int e = 0; e < 4; ++e)
            cp16b(sa + e * 32 * (ASTRIDE * 2), g + (size_t)e * 32 * LL);
    }
}

__global__ __launch_bounds__(256, 1) void k_main(float* __restrict__ out) {
    extern __shared__ __half sm[];
    const uint32_t sbase = smem_u32(sm);
    const int t = threadIdx.x;
    const int lane = t & 31, wid = t >> 5;
    const int wm = wid >> 2, wn = wid & 3;     // 2x4 warp grid, warp tile 64x32
    const int lr = lane >> 2, lc = lane & 3;
    const int i0 = blockIdx.y * 128, j0 = blockIdx.x * 128;

    float numer[4][4][4], denom[4][4][4];
#pragma unroll
    for (int a = 0; a < 4; ++a)
#pragma unroll
        for (int b = 0; b < 4; ++b)
#pragma unroll
            for (int c = 0; c < 4; ++c) { numer[a][b][c] = 0.f; denom[a][b][c] = 0.f; }

    const int a_row_l = lane & 15;
    const int a_col_l = (lane >> 4) * 8;
    const int b_row_l = (lane & 7) + ((lane >> 4) << 3);
    const int b_col_l = ((lane >> 3) & 1) * 8;

    load_stage_m(sbase, i0, j0, 0, t);
    asm volatile("cp.async.commit_group;");

#pragma unroll 1
    for (int kt = 0; kt < NKT; ++kt) {
        const int st = kt & 1;
        if (kt + 1 < NKT) {
            load_stage_m(sbase + (st ^ 1) * STAGE_B, i0, j0, (kt + 1) * KC, t);
            asm volatile("cp.async.commit_group;");
            asm volatile("cp.async.wait_group 1;");
        } else {
            asm volatile("cp.async.wait_group 0;");
        }
        __syncthreads();

        const uint32_t sb = sbase + st * STAGE_B;
#pragma unroll
        for (int kh = 0; kh < 4; ++kh) {
            const int kofs = kh * 16;
            uint32_t BG[2][4], BH[2][4];
#pragma unroll
            for (int n2 = 0; n2 < 2; ++n2) {
                const int brow = wn * 32 + n2 * 16 + b_row_l;
                const uint32_t bo = (uint32_t)(brow * ASTRIDE + kofs + b_col_l) * 2;
                ldsm4(BG[n2], sb + 3 * TILE_B + bo);
                ldsm4(BH[n2], sb + 4 * TILE_B + bo);
            }
            uint32_t A[2][3][4];   // [buf][sHi/sLo/s2][frag] — software-pipelined
            {
                const int arow = wm * 64 + a_row_l;
                const uint32_t ao = (uint32_t)(arow * ASTRIDE + kofs + a_col_l) * 2;
                ldsm4(A[0][0], sb + 0 * TILE_B + ao);
                ldsm4(A[0][1], sb + 1 * TILE_B + ao);
                ldsm4(A[0][2], sb + 2 * TILE_B + ao);
            }
#pragma unroll
            for (int mt = 0; mt < 4; ++mt) {
                if (mt < 3) {   // prefetch next mt's fragments under current MMAs
                    const int arow = wm * 64 + (mt + 1) * 16 + a_row_l;
                    const uint32_t ao = (uint32_t)(arow * ASTRIDE + kofs + a_col_l) * 2;
                    ldsm4(A[(mt + 1) & 1][0], sb + 0 * TILE_B + ao);
                    ldsm4(A[(mt + 1) & 1][1], sb + 1 * TILE_B + ao);
                    ldsm4(A[(mt + 1) & 1][2], sb + 2 * TILE_B + ao);
                }
                const int bf = mt & 1;
#pragma unroll
                for (int nt = 0; nt < 4; ++nt)
                    mma_f16(numer[mt][nt], A[bf][0], BG[nt >> 1][2 * (nt & 1)], BG[nt >> 1][2 * (nt & 1) + 1]);
#pragma unroll
                for (int nt = 0; nt < 4; ++nt)
                    mma_f16(numer[mt][nt], A[bf][1], BG[nt >> 1][2 * (nt & 1)], BG[nt >> 1][2 * (nt & 1) + 1]);
#pragma unroll
                for (int nt = 0; nt < 4; ++nt)
                    mma_f16(denom[mt][nt], A[bf][2], BH[nt >> 1][2 * (nt & 1)], BH[nt >> 1][2 * (nt & 1) + 1]);
            }
        }
        __syncthreads();
    }

    // epilogue
#pragma unroll
    for (int mt = 0; mt < 4; ++mt)
#pragma unroll
        for (int nt = 0; nt < 4; ++nt) {
            const int i = i0 + wm * 64 + mt * 16 + lr;
            const int j = j0 + wn * 32 + nt * 8 + lc * 2;
            float2 v0, v1;
            v0.x = numer[mt][nt][0] * rsqrtf(denom[mt][nt][0]);
            v0.y = numer[mt][nt][1] * rsqrtf(denom[mt][nt][1]);
            v1.x = numer[mt][nt][2] * rsqrtf(denom[mt][nt][2]);
            v1.y = numer[mt][nt][3] * rsqrtf(denom[mt][nt][3]);
            *reinterpret_cast<float2*>(out + (size_t)i * BSZ + j) = v0;
            *reinterpret_cast<float2*>(out + (size_t)(i + 8) * BSZ + j) = v1;
        }
}

// ---------------- launch ----------------
extern "C" void kernel_launch(void* const* d_in, const int* in_sizes, int n_in,
                              void* d_out, int out_size) {
    (void)in_sizes; (void)n_in; (void)out_size;
    const float* img  = (const float*)d_in[0];
    const float* cap  = (const float*)d_in[1];
    // d_in[2] = lens : unused by the reference computation
    const float* Wred = (const float*)d_in[3];
    const float* bred = (const float*)d_in[4];
    const float* Wkp  = (const float*)d_in[5];
    const float* bkp  = (const float*)d_in[6];
    float* out = (float*)d_out;

    k_sum<<<BSZ, 256>>>(img);
    k_norm<<<BSZ, 256>>>(cap);
    k_repr<<<BSZ / 8, 256>>>(cap, Wred, bred);
    k_wsplit<<<(LL * LK / 4) / 256, 256>>>(Wkp);

    cudaFuncSetAttribute(k_gate, cudaFuncAttributeMaxDynamicSharedMemorySize, SMEM_GATE);
    k_gate<<<dim3(LL / 128, BSZ / 128), 256, SMEM_GATE>>>(cap, bkp);

    cudaFuncSetAttribute(k_main, cudaFuncAttributeMaxDynamicSharedMemorySize, SMEM_MAIN);
    k_main<<<dim3(BSZ / 128, BSZ / 128), 256, SMEM_MAIN>>>(out);
}

// round 12
// speedup vs baseline: 1.7724x; 1.1524x over previous
#include <cuda_runtime.h>
#include <cuda_fp16.h>
#include <cstdint>

#define BSZ 4096
#define RR 36
#define TT 32
#define LL 1024
#define LK 256

// ---------------- scratch (__device__ globals; no allocations allowed) ----------------
__device__ __half g_sHi[BSZ * LL];   // fp16(s)
__device__ __half g_s2[BSZ * LL];    // fp16(s*s)
__device__ __half g_gg[BSZ * LL];    // fp16(gate * c_hat)
__device__ __half g_hh[BSZ * LL];    // fp16(gate*gate)
__device__ __half g_rHi[BSZ * LK];   // fp16(cap_repr)
__device__ __half g_rLo[BSZ * LK];   // fp16(residual)
__device__ __half g_wH[LL * LK];     // fp16(W_kp)
__device__ float g_invn[BSZ];

// ---------------- helpers ----------------
__device__ __forceinline__ uint32_t smem_u32(const void* p) {
    uint32_t a;
    asm("{ .reg .u64 t; cvta.to.shared.u64 t, %1; cvt.u32.u64 %0, t; }" : "=r"(a) : "l"(p));
    return a;
}
__device__ __forceinline__ void cp16b(uint32_t sa, const void* g) {
    asm volatile("cp.async.cg.shared.global [%0], [%1], 16;" ::"r"(sa), "l"(g));
}
__device__ __forceinline__ void ldsm4(uint32_t r[4], uint32_t sa) {
    asm volatile("ldmatrix.sync.aligned.m8n8.x4.shared.b16 {%0,%1,%2,%3}, [%4];"
                 : "=r"(r[0]), "=r"(r[1]), "=r"(r[2]), "=r"(r[3]) : "r"(sa));
}
__device__ __forceinline__ void mma_f16(float d[4], const uint32_t a[4],
                                        uint32_t b0, uint32_t b1) {
    asm("mma.sync.aligned.m16n8k16.row.col.f32.f16.f16.f32 "
        "{%0,%1,%2,%3}, {%4,%5,%6,%7}, {%8,%9}, {%0,%1,%2,%3};"
        : "+f"(d[0]), "+f"(d[1]), "+f"(d[2]), "+f"(d[3])
        : "r"(a[0]), "r"(a[1]), "r"(a[2]), "r"(a[3]), "r"(b0), "r"(b1));
}

// ---------------- K1: s = img.sum(axis=1), emit fp16 s and s^2 ----------------
__global__ void k_sum(const float* __restrict__ img) {
    const int b = blockIdx.x, t = threadIdx.x;
    const float4* p = reinterpret_cast<const float4*>(img + (size_t)b * RR * LL) + t;
    float4 acc = make_float4(0.f, 0.f, 0.f, 0.f);
#pragma unroll
    for (int r = 0; r < RR; ++r) {
        float4 v = p[r * (LL / 4)];
        acc.x += v.x; acc.y += v.y; acc.z += v.z; acc.w += v.w;
    }
    const size_t o = (size_t)b * LL + t * 4;
    float s[4] = {acc.x, acc.y, acc.z, acc.w};
#pragma unroll
    for (int c = 0; c < 4; ++c) {
        g_sHi[o + c] = __float2half(s[c]);
        g_s2[o + c]  = __float2half(s[c] * s[c]);
    }
}

// ---------------- K2: inv_norm of cap0 rows ----------------
__global__ void k_norm(const float* __restrict__ cap) {
    const int b = blockIdx.x, t = threadIdx.x;
    const float4 v = reinterpret_cast<const float4*>(cap + (size_t)b * TT * LL)[t];
    float ss = v.x * v.x + v.y * v.y + v.z * v.z + v.w * v.w;
#pragma unroll
    for (int o = 16; o; o >>= 1) ss += __shfl_xor_sync(0xffffffffu, ss, o);
    __shared__ float red[8];
    if ((t & 31) == 0) red[t >> 5] = ss;
    __syncthreads();
    if (t == 0) {
        float tot = 0.f;
#pragma unroll
        for (int w = 0; w < 8; ++w) tot += red[w];
        g_invn[b] = rsqrtf(tot);
    }
}

// ---------------- K3: cap_repr = cap0 @ W_red^T + b_red (emit fp16 splits) ----------------
__global__ __launch_bounds__(256) void k_repr(const float* __restrict__ cap,
                                              const float* __restrict__ Wred,
                                              const float* __restrict__ bred) {
    __shared__ float sc[8][LL];
    const int b0 = blockIdx.x * 8, t = threadIdx.x;
#pragma unroll
    for (int bb = 0; bb < 8; ++bb)
        reinterpret_cast<float4*>(sc[bb])[t] =
            reinterpret_cast<const float4*>(cap + (size_t)(b0 + bb) * TT * LL)[t];
    __syncthreads();

    float acc[8] = {0.f, 0.f, 0.f, 0.f, 0.f, 0.f, 0.f, 0.f};
    const float4* w = reinterpret_cast<const float4*>(Wred + (size_t)t * LL);
    for (int k4 = 0; k4 < LL / 4; ++k4) {
        const float4 wv = w[k4];
#pragma unroll
        for (int bb = 0; bb < 8; ++bb) {
            const float4 cv = reinterpret_cast<const float4*>(sc[bb])[k4];
            acc[bb] += wv.x * cv.x + wv.y * cv.y + wv.z * cv.z + wv.w * cv.w;
        }
    }
    const float bias = bred[t];
#pragma unroll
    for (int bb = 0; bb < 8; ++bb) {
        const float v = acc[bb] + bias;
        const __half hi = __float2half(v);
        const __half lo = __float2half(v - __half2float(hi));
        g_rHi[(size_t)(b0 + bb) * LK + t] = hi;
        g_rLo[(size_t)(b0 + bb) * LK + t] = lo;
    }
}

// ---------------- K3b: Wkp -> fp16 ----------------
__global__ void k_wsplit(const float* __restrict__ Wkp) {
    const int i = blockIdx.x * 256 + threadIdx.x;     // float4 index
    const float4 v = reinterpret_cast<const float4*>(Wkp)[i];
    __half2 h0 = __floats2half2_rn(v.x, v.y);
    __half2 h1 = __floats2half2_rn(v.z, v.w);
    uint2 pk;
    pk.x = *reinterpret_cast<uint32_t*>(&h0);
    pk.y = *reinterpret_cast<uint32_t*>(&h1);
    *reinterpret_cast<uint2*>(g_wH + (size_t)i * 4) = pk;
}

// ---------------- K4: gate via split-fp16 HMMA; fused sigmoid epilogue ----------------
// z[b,l] = (rHi+rLo)[b,:] . wH[l,:],  K=256
#define GKC 64
#define GSTR 72                       // fp16 elems per smem row (144B) — conflict-free LDSM
#define GTILE (128 * GSTR)            // elems
#define GTILE_B (GTILE * 2)           // bytes
#define GNARR 3                       // rHi, rLo | wH
#define GSTAGE_B (GNARR * GTILE_B)    // 55296 B
#define GNKT (LK / GKC)               // 4
#define SMEM_GATE (2 * GSTAGE_B)      // 110592 B

__device__ __forceinline__ void load_stage_g(uint32_t sstage, int i0, int j0, int k0, int t) {
    const int c = t & 7;              // 16B chunk within 128B of k
    const int r0 = t >> 3;            // 0..31
    const __half* srcs[GNARR] = {g_rHi, g_rLo, g_wH};
#pragma unroll
    for (int a = 0; a < GNARR; ++a) {
        const int base = (a < 2) ? i0 : j0;
        const __half* g = srcs[a] + (size_t)(base + r0) * LK + k0 + c * 8;
        const uint32_t sa = sstage + a * GTILE_B + r0 * (GSTR * 2) + c * 16;
#pragma unroll
        for (int e = 0; e < 4; ++e)
            cp16b(sa + e * 32 * (GSTR * 2), g + (size_t)e * 32 * LK);
    }
}

__global__ __launch_bounds__(256, 1) void k_gate(const float* __restrict__ cap,
                                                 const float* __restrict__ bkp) {
    extern __shared__ __half smg[];
    const uint32_t sbase = smem_u32(smg);
    const int t = threadIdx.x;
    const int lane = t & 31, wid = t >> 5;
    const int wm = wid >> 2, wn = wid & 3;     // 2x4 warp grid, warp tile 64x32
    const int lr = lane >> 2, lc = lane & 3;
    const int i0 = blockIdx.y * 128;           // batch
    const int j0 = blockIdx.x * 128;           // l feature

    float z[4][4][4];
#pragma unroll
    for (int a = 0; a < 4; ++a)
#pragma unroll
        for (int b = 0; b < 4; ++b)
#pragma unroll
            for (int c = 0; c < 4; ++c) z[a][b][c] = 0.f;

    const int a_row_l = lane & 15;
    const int a_col_l = (lane >> 4) * 8;
    const int b_row_l = (lane & 7) + ((lane >> 4) << 3);
    const int b_col_l = ((lane >> 3) & 1) * 8;

    load_stage_g(sbase, i0, j0, 0, t);
    asm volatile("cp.async.commit_group;");

#pragma unroll 1
    for (int kt = 0; kt < GNKT; ++kt) {
        const int st = kt & 1;
        if (kt + 1 < GNKT) {
            load_stage_g(sbase + (st ^ 1) * GSTAGE_B, i0, j0, (kt + 1) * GKC, t);
            asm volatile("cp.async.commit_group;");
            asm volatile("cp.async.wait_group 1;");
        } else {
            asm volatile("cp.async.wait_group 0;");
        }
        __syncthreads();
        const uint32_t sb = sbase + st * GSTAGE_B;
#pragma unroll
        for (int kh = 0; kh < 4; ++kh) {
            const int kofs = kh * 16;
            uint32_t BW[2][4];
#pragma unroll
            for (int n2 = 0; n2 < 2; ++n2) {
                const int brow = wn * 32 + n2 * 16 + b_row_l;
                ldsm4(BW[n2], sb + 2 * GTILE_B + (uint32_t)(brow * GSTR + kofs + b_col_l) * 2);
            }
            uint32_t A[2][2][4];   // [buf][hi/lo][frag]
            {
                const int arow = wm * 64 + a_row_l;
                const uint32_t ao = (uint32_t)(arow * GSTR + kofs + a_col_l) * 2;
                ldsm4(A[0][0], sb + 0 * GTILE_B + ao);
                ldsm4(A[0][1], sb + 1 * GTILE_B + ao);
            }
#pragma unroll
            for (int mt = 0; mt < 4; ++mt) {
                if (mt < 3) {
                    const int arow = wm * 64 + (mt + 1) * 16 + a_row_l;
                    const uint32_t ao = (uint32_t)(arow * GSTR + kofs + a_col_l) * 2;
                    ldsm4(A[(mt + 1) & 1][0], sb + 0 * GTILE_B + ao);
                    ldsm4(A[(mt + 1) & 1][1], sb + 1 * GTILE_B + ao);
                }
#pragma unroll
                for (int nt = 0; nt < 4; ++nt)
                    mma_f16(z[mt][nt], A[mt & 1][0], BW[nt >> 1][2 * (nt & 1)], BW[nt >> 1][2 * (nt & 1) + 1]);
#pragma unroll
                for (int nt = 0; nt < 4; ++nt)
                    mma_f16(z[mt][nt], A[mt & 1][1], BW[nt >> 1][2 * (nt & 1)], BW[nt >> 1][2 * (nt & 1) + 1]);
            }
        }
        __syncthreads();
    }

    // epilogue: sigmoid + combine with c_hat; emit gg, hh (fp16)
#pragma unroll
    for (int mt = 0; mt < 4; ++mt)
#pragma unroll
        for (int nt = 0; nt < 4; ++nt) {
            const int j = j0 + wn * 32 + nt * 8 + lc * 2;
            const float2 bb = *reinterpret_cast<const float2*>(bkp + j);
#pragma unroll
            for (int h = 0; h < 2; ++h) {
                const int i = i0 + wm * 64 + mt * 16 + lr + h * 8;
                const float inv = g_invn[i];
                const float2 cv = *reinterpret_cast<const float2*>(cap + (size_t)i * TT * LL + j);
                const float z0 = z[mt][nt][2 * h + 0] + bb.x;
                const float z1 = z[mt][nt][2 * h + 1] + bb.y;
                const float gt0 = 1.0f / (1.0f + expf(-z0));
                const float gt1 = 1.0f / (1.0f + expf(-z1));
                __half2 gg = __floats2half2_rn(gt0 * cv.x * inv, gt1 * cv.y * inv);
                __half2 hh = __floats2half2_rn(gt0 * gt0, gt1 * gt1);
                *reinterpret_cast<__half2*>(g_gg + (size_t)i * LL + j) = gg;
                *reinterpret_cast<__half2*>(g_hh + (size_t)i * LL + j) = hh;
            }
        }
}

// ---------------- K5: fused dual GEMM, ldmatrix + mma.sync (fp16, 2 products) ----------------
#define KC 64
#define ASTRIDE 72                    // fp16 elems per smem row (144B) — conflict-free LDSM
#define TILEE (128 * ASTRIDE)         // 9216 elems per array tile
#define TILE_B (TILEE * 2)            // 18432 bytes
#define NARR 4                        // sHi, s2 | gg, hh
#define STAGE_B (NARR * TILE_B)       // 73728 B per stage
#define NKT (LL / KC)                 // 16
#define SMEM_MAIN (2 * STAGE_B)       // 147456 B

__device__ __forceinline__ void load_stage_m(uint32_t sstage, int i0, int j0, int k0, int t) {
    const int c = t & 7;              // 16B chunk within 128B of k
    const int r0 = t >> 3;            // 0..31
    const __half* srcs[NARR] = {g_sHi, g_s2, g_gg, g_hh};
#pragma unroll
    for (int a = 0; a < NARR; ++a) {
        const int base = (a < 2) ? i0 : j0;
        const __half* g = srcs[a] + (size_t)(base + r0) * LL + k0 + c * 8;
        const uint32_t sa = sstage + a * TILE_B + r0 * (ASTRIDE * 2) + c * 16;
#pragma unroll
        for (int e = 0; e < 4; ++e)
            cp16b(sa + e * 32 * (ASTRIDE * 2), g + (size_t)e * 32 * LL);
    }
}

__global__ __launch_bounds__(256, 1) void k_main(float* __restrict__ out) {
    extern __shared__ __half sm[];
    const uint32_t sbase = smem_u32(sm);
    const int t = threadIdx.x;
    const int lane = t & 31, wid = t >> 5;
    const int wm = wid >> 2, wn = wid & 3;     // 2x4 warp grid, warp tile 64x32
    const int lr = lane >> 2, lc = lane & 3;
    const int i0 = blockIdx.y * 128, j0 = blockIdx.x * 128;

    float numer[4][4][4], denom[4][4][4];
#pragma unroll
    for (int a = 0; a < 4; ++a)
#pragma unroll
        for (int b = 0; b < 4; ++b)
#pragma unroll
            for (int c = 0; c < 4; ++c) { numer[a][b][c] = 0.f; denom[a][b][c] = 0.f; }

    const int a_row_l = lane & 15;
    const int a_col_l = (lane >> 4) * 8;
    const int b_row_l = (lane & 7) + ((lane >> 4) << 3);
    const int b_col_l = ((lane >> 3) & 1) * 8;

    load_stage_m(sbase, i0, j0, 0, t);
    asm volatile("cp.async.commit_group;");

#pragma unroll 1
    for (int kt = 0; kt < NKT; ++kt) {
        const int st = kt & 1;
        if (kt + 1 < NKT) {
            load_stage_m(sbase + (st ^ 1) * STAGE_B, i0, j0, (kt + 1) * KC, t);
            asm volatile("cp.async.commit_group;");
            asm volatile("cp.async.wait_group 1;");
        } else {
            asm volatile("cp.async.wait_group 0;");
        }
        __syncthreads();

        const uint32_t sb = sbase + st * STAGE_B;
#pragma unroll
        for (int kh = 0; kh < 4; ++kh) {
            const int kofs = kh * 16;
            uint32_t BG[2][4], BH[2][4];
#pragma unroll
            for (int n2 = 0; n2 < 2; ++n2) {
                const int brow = wn * 32 + n2 * 16 + b_row_l;
                const uint32_t bo = (uint32_t)(brow * ASTRIDE + kofs + b_col_l) * 2;
                ldsm4(BG[n2], sb + 2 * TILE_B + bo);
                ldsm4(BH[n2], sb + 3 * TILE_B + bo);
            }
            uint32_t A[2][2][4];   // [buf][sHi/s2][frag] — software-pipelined
            {
                const int arow = wm * 64 + a_row_l;
                const uint32_t ao = (uint32_t)(arow * ASTRIDE + kofs + a_col_l) * 2;
                ldsm4(A[0][0], sb + 0 * TILE_B + ao);
                ldsm4(A[0][1], sb + 1 * TILE_B + ao);
            }
#pragma unroll
            for (int mt = 0; mt < 4; ++mt) {
                if (mt < 3) {   // prefetch next mt's fragments under current MMAs
                    const int arow = wm * 64 + (mt + 1) * 16 + a_row_l;
                    const uint32_t ao = (uint32_t)(arow * ASTRIDE + kofs + a_col_l) * 2;
                    ldsm4(A[(mt + 1) & 1][0], sb + 0 * TILE_B + ao);
                    ldsm4(A[(mt + 1) & 1][1], sb + 1 * TILE_B + ao);
                }
                const int bf = mt & 1;
#pragma unroll
                for (int nt = 0; nt < 4; ++nt)
                    mma_f16(numer[mt][nt], A[bf][0], BG[nt >> 1][2 * (nt & 1)], BG[nt >> 1][2 * (nt & 1) + 1]);
#pragma unroll
                for (int nt = 0; nt < 4; ++nt)
                    mma_f16(denom[mt][nt], A[bf][1], BH[nt >> 1][2 * (nt & 1)], BH[nt >> 1][2 * (nt & 1) + 1]);
            }
        }
        __syncthreads();
    }

    // epilogue
#pragma unroll
    for (int mt = 0; mt < 4; ++mt)
#pragma unroll
        for (int nt = 0; nt < 4; ++nt) {
            const int i = i0 + wm * 64 + mt * 16 + lr;
            const int j = j0 + wn * 32 + nt * 8 + lc * 2;
            float2 v0, v1;
            v0.x = numer[mt][nt][0] * rsqrtf(denom[mt][nt][0]);
            v0.y = numer[mt][nt][1] * rsqrtf(denom[mt][nt][1]);
            v1.x = numer[mt][nt][2] * rsqrtf(denom[mt][nt][2]);
            v1.y = numer[mt][nt][3] * rsqrtf(denom[mt][nt][3]);
            *reinterpret_cast<float2*>(out + (size_t)i * BSZ + j) = v0;
            *reinterpret_cast<float2*>(out + (size_t)(i + 8) * BSZ + j) = v1;
        }
}

// ---------------- launch ----------------
extern "C" void kernel_launch(void* const* d_in, const int* in_sizes, int n_in,
                              void* d_out, int out_size) {
    (void)in_sizes; (void)n_in; (void)out_size;
    const float* img  = (const float*)d_in[0];
    const float* cap  = (const float*)d_in[1];
    // d_in[2] = lens : unused by the reference computation
    const float* Wred = (const float*)d_in[3];
    const float* bred = (const float*)d_in[4];
    const float* Wkp  = (const float*)d_in[5];
    const float* bkp  = (const float*)d_in[6];
    float* out = (float*)d_out;

    k_sum<<<BSZ, 256>>>(img);
    k_norm<<<BSZ, 256>>>(cap);
    k_repr<<<BSZ / 8, 256>>>(cap, Wred, bred);
    k_wsplit<<<(LL * LK / 4) / 256, 256>>>(Wkp);

    cudaFuncSetAttribute(k_gate, cudaFuncAttributeMaxDynamicSharedMemorySize, SMEM_GATE);
    k_gate<<<dim3(LL / 128, BSZ / 128), 256, SMEM_GATE>>>(cap, bkp);

    cudaFuncSetAttribute(k_main, cudaFuncAttributeMaxDynamicSharedMemorySize, SMEM_MAIN);
    k_main<<<dim3(BSZ / 128, BSZ / 128), 256, SMEM_MAIN>>>(out);
}

// round 14
// speedup vs baseline: 1.7925x; 1.0113x over previous
#include <cuda_runtime.h>
#include <cuda_fp16.h>
#include <cstdint>

#define BSZ 4096
#define RR 36
#define TT 32
#define LL 1024
#define LK 256

// ---------------- scratch (__device__ globals; no allocations allowed) ----------------
__device__ __half g_sHi[BSZ * LL];   // fp16(s)
__device__ __half g_s2[BSZ * LL];    // fp16(s*s)
__device__ __half g_gg[BSZ * LL];    // fp16(gate * c_hat)
__device__ __half g_hh[BSZ * LL];    // fp16(gate*gate)
__device__ __half g_rHi[BSZ * LK];   // fp16(cap_repr)
__device__ __half g_rLo[BSZ * LK];   // fp16(residual)
__device__ __half g_wH[LL * LK];     // fp16(W_kp)
__device__ float g_invn[BSZ];

// ---------------- helpers ----------------
__device__ __forceinline__ uint32_t smem_u32(const void* p) {
    uint32_t a;
    asm("{ .reg .u64 t; cvta.to.shared.u64 t, %1; cvt.u32.u64 %0, t; }" : "=r"(a) : "l"(p));
    return a;
}
__device__ __forceinline__ void cp16b(uint32_t sa, const void* g) {
    asm volatile("cp.async.cg.shared.global [%0], [%1], 16;" ::"r"(sa), "l"(g));
}
__device__ __forceinline__ void ldsm4(uint32_t r[4], uint32_t sa) {
    asm volatile("ldmatrix.sync.aligned.m8n8.x4.shared.b16 {%0,%1,%2,%3}, [%4];"
                 : "=r"(r[0]), "=r"(r[1]), "=r"(r[2]), "=r"(r[3]) : "r"(sa));
}
__device__ __forceinline__ void mma_f16(float d[4], const uint32_t a[4],
                                        uint32_t b0, uint32_t b1) {
    asm("mma.sync.aligned.m16n8k16.row.col.f32.f16.f16.f32 "
        "{%0,%1,%2,%3}, {%4,%5,%6,%7}, {%8,%9}, {%0,%1,%2,%3};"
        : "+f"(d[0]), "+f"(d[1]), "+f"(d[2]), "+f"(d[3])
        : "r"(a[0]), "r"(a[1]), "r"(a[2]), "r"(a[3]), "r"(b0), "r"(b1));
}

// ---------------- K1: s = img.sum(axis=1), emit fp16 s and s^2 ----------------
__global__ void k_sum(const float* __restrict__ img) {
    const int b = blockIdx.x, t = threadIdx.x;
    const float4* p = reinterpret_cast<const float4*>(img + (size_t)b * RR * LL) + t;
    float4 acc = make_float4(0.f, 0.f, 0.f, 0.f);
#pragma unroll
    for (int r = 0; r < RR; ++r) {
        float4 v = p[r * (LL / 4)];
        acc.x += v.x; acc.y += v.y; acc.z += v.z; acc.w += v.w;
    }
    const size_t o = (size_t)b * LL + t * 4;
    float s[4] = {acc.x, acc.y, acc.z, acc.w};
#pragma unroll
    for (int c = 0; c < 4; ++c) {
        g_sHi[o + c] = __float2half(s[c]);
        g_s2[o + c]  = __float2half(s[c] * s[c]);
    }
}

// ---------------- K2: inv_norm of cap0 rows ----------------
__global__ void k_norm(const float* __restrict__ cap) {
    const int b = blockIdx.x, t = threadIdx.x;
    const float4 v = reinterpret_cast<const float4*>(cap + (size_t)b * TT * LL)[t];
    float ss = v.x * v.x + v.y * v.y + v.z * v.z + v.w * v.w;
#pragma unroll
    for (int o = 16; o; o >>= 1) ss += __shfl_xor_sync(0xffffffffu, ss, o);
    __shared__ float red[8];
    if ((t & 31) == 0) red[t >> 5] = ss;
    __syncthreads();
    if (t == 0) {
        float tot = 0.f;
#pragma unroll
        for (int w = 0; w < 8; ++w) tot += red[w];
        g_invn[b] = rsqrtf(tot);
    }
}

// ---------------- K3: cap_repr = cap0 @ W_red^T + b_red (emit fp16 splits) ----------------
__global__ __launch_bounds__(256) void k_repr(const float* __restrict__ cap,
                                              const float* __restrict__ Wred,
                                              const float* __restrict__ bred) {
    __shared__ float sc[8][LL];
    const int b0 = blockIdx.x * 8, t = threadIdx.x;
#pragma unroll
    for (int bb = 0; bb < 8; ++bb)
        reinterpret_cast<float4*>(sc[bb])[t] =
            reinterpret_cast<const float4*>(cap + (size_t)(b0 + bb) * TT * LL)[t];
    __syncthreads();

    float acc[8] = {0.f, 0.f, 0.f, 0.f, 0.f, 0.f, 0.f, 0.f};
    const float4* w = reinterpret_cast<const float4*>(Wred + (size_t)t * LL);
    for (int k4 = 0; k4 < LL / 4; ++k4) {
        const float4 wv = w[k4];
#pragma unroll
        for (int bb = 0; bb < 8; ++bb) {
            const float4 cv = reinterpret_cast<const float4*>(sc[bb])[k4];
            acc[bb] += wv.x * cv.x + wv.y * cv.y + wv.z * cv.z + wv.w * cv.w;
        }
    }
    const float bias = bred[t];
#pragma unroll
    for (int bb = 0; bb < 8; ++bb) {
        const float v = acc[bb] + bias;
        const __half hi = __float2half(v);
        const __half lo = __float2half(v - __half2float(hi));
        g_rHi[(size_t)(b0 + bb) * LK + t] = hi;
        g_rLo[(size_t)(b0 + bb) * LK + t] = lo;
    }
}

// ---------------- K3b: Wkp -> fp16 ----------------
__global__ void k_wsplit(const float* __restrict__ Wkp) {
    const int i = blockIdx.x * 256 + threadIdx.x;     // float4 index
    const float4 v = reinterpret_cast<const float4*>(Wkp)[i];
    __half2 h0 = __floats2half2_rn(v.x, v.y);
    __half2 h1 = __floats2half2_rn(v.z, v.w);
    uint2 pk;
    pk.x = *reinterpret_cast<uint32_t*>(&h0);
    pk.y = *reinterpret_cast<uint32_t*>(&h1);
    *reinterpret_cast<uint2*>(g_wH + (size_t)i * 4) = pk;
}

// ---------------- K4: gate via split-fp16 HMMA; fused sigmoid epilogue ----------------
// z[b,l] = (rHi+rLo)[b,:] . wH[l,:],  K=256
#define GKC 64
#define GSTR 72                       // fp16 elems per smem row (144B) — conflict-free LDSM
#define GTILE (128 * GSTR)            // elems
#define GTILE_B (GTILE * 2)           // bytes
#define GNARR 3                       // rHi, rLo | wH
#define GSTAGE_B (GNARR * GTILE_B)    // 55296 B
#define GNKT (LK / GKC)               // 4
#define SMEM_GATE (2 * GSTAGE_B)      // 110592 B

__device__ __forceinline__ void load_stage_g(uint32_t sstage, int i0, int j0, int k0, int t) {
    const int c = t & 7;              // 16B chunk within 128B of k
    const int r0 = t >> 3;            // 0..31
    const __half* srcs[GNARR] = {g_rHi, g_rLo, g_wH};
#pragma unroll
    for (int a = 0; a < GNARR; ++a) {
        const int base = (a < 2) ? i0 : j0;
        const __half* g = srcs[a] + (size_t)(base + r0) * LK + k0 + c * 8;
        const uint32_t sa = sstage + a * GTILE_B + r0 * (GSTR * 2) + c * 16;
#pragma unroll
        for (int e = 0; e < 4; ++e)
            cp16b(sa + e * 32 * (GSTR * 2), g + (size_t)e * 32 * LK);
    }
}

__global__ __launch_bounds__(256, 1) void k_gate(const float* __restrict__ cap,
                                                 const float* __restrict__ bkp) {
    extern __shared__ __half smg[];
    const uint32_t sbase = smem_u32(smg);
    const int t = threadIdx.x;
    const int lane = t & 31, wid = t >> 5;
    const int wm = wid >> 2, wn = wid & 3;     // 2x4 warp grid, warp tile 64x32
    const int lr = lane >> 2, lc = lane & 3;
    const int i0 = blockIdx.y * 128;           // batch
    const int j0 = blockIdx.x * 128;           // l feature

    float z[4][4][4];
#pragma unroll
    for (int a = 0; a < 4; ++a)
#pragma unroll
        for (int b = 0; b < 4; ++b)
#pragma unroll
            for (int c = 0; c < 4; ++c) z[a][b][c] = 0.f;

    const int a_row_l = lane & 15;
    const int a_col_l = (lane >> 4) * 8;
    const int b_row_l = (lane & 7) + ((lane >> 4) << 3);
    const int b_col_l = ((lane >> 3) & 1) * 8;

    load_stage_g(sbase, i0, j0, 0, t);
    asm volatile("cp.async.commit_group;");

#pragma unroll 1
    for (int kt = 0; kt < GNKT; ++kt) {
        const int st = kt & 1;
        if (kt + 1 < GNKT) {
            load_stage_g(sbase + (st ^ 1) * GSTAGE_B, i0, j0, (kt + 1) * GKC, t);
            asm volatile("cp.async.commit_group;");
            asm volatile("cp.async.wait_group 1;");
        } else {
            asm volatile("cp.async.wait_group 0;");
        }
        __syncthreads();
        const uint32_t sb = sbase + st * GSTAGE_B;
#pragma unroll
        for (int kh = 0; kh < 4; ++kh) {
            const int kofs = kh * 16;
            uint32_t BW[2][4];
#pragma unroll
            for (int n2 = 0; n2 < 2; ++n2) {
                const int brow = wn * 32 + n2 * 16 + b_row_l;
                ldsm4(BW[n2], sb + 2 * GTILE_B + (uint32_t)(brow * GSTR + kofs + b_col_l) * 2);
            }
            uint32_t A[2][2][4];   // [buf][hi/lo][frag]
            {
                const int arow = wm * 64 + a_row_l;
                const uint32_t ao = (uint32_t)(arow * GSTR + kofs + a_col_l) * 2;
                ldsm4(A[0][0], sb + 0 * GTILE_B + ao);
                ldsm4(A[0][1], sb + 1 * GTILE_B + ao);
            }
#pragma unroll
            for (int mt = 0; mt < 4; ++mt) {
                if (mt < 3) {
                    const int arow = wm * 64 + (mt + 1) * 16 + a_row_l;
                    const uint32_t ao = (uint32_t)(arow * GSTR + kofs + a_col_l) * 2;
                    ldsm4(A[(mt + 1) & 1][0], sb + 0 * GTILE_B + ao);
                    ldsm4(A[(mt + 1) & 1][1], sb + 1 * GTILE_B + ao);
                }
#pragma unroll
                for (int nt = 0; nt < 4; ++nt)
                    mma_f16(z[mt][nt], A[mt & 1][0], BW[nt >> 1][2 * (nt & 1)], BW[nt >> 1][2 * (nt & 1) + 1]);
#pragma unroll
                for (int nt = 0; nt < 4; ++nt)
                    mma_f16(z[mt][nt], A[mt & 1][1], BW[nt >> 1][2 * (nt & 1)], BW[nt >> 1][2 * (nt & 1) + 1]);
            }
        }
        __syncthreads();
    }

    // epilogue: sigmoid + combine with c_hat; emit gg, hh (fp16)
#pragma unroll
    for (int mt = 0; mt < 4; ++mt)
#pragma unroll
        for (int nt = 0; nt < 4; ++nt) {
            const int j = j0 + wn * 32 + nt * 8 + lc * 2;
            const float2 bb = *reinterpret_cast<const float2*>(bkp + j);
#pragma unroll
            for (int h = 0; h < 2; ++h) {
                const int i = i0 + wm * 64 + mt * 16 + lr + h * 8;
                const float inv = g_invn[i];
                const float2 cv = *reinterpret_cast<const float2*>(cap + (size_t)i * TT * LL + j);
                const float z0 = z[mt][nt][2 * h + 0] + bb.x;
                const float z1 = z[mt][nt][2 * h + 1] + bb.y;
                const float gt0 = 1.0f / (1.0f + expf(-z0));
                const float gt1 = 1.0f / (1.0f + expf(-z1));
                __half2 gg = __floats2half2_rn(gt0 * cv.x * inv, gt1 * cv.y * inv);
                __half2 hh = __floats2half2_rn(gt0 * gt0, gt1 * gt1);
                *reinterpret_cast<__half2*>(g_gg + (size_t)i * LL + j) = gg;
                *reinterpret_cast<__half2*>(g_hh + (size_t)i * LL + j) = hh;
            }
        }
}

// ---------------- K5: fused dual GEMM, ldmatrix + mma.sync (fp16, 2 products) ----------------
// 3-stage cp.async pipeline, single __syncthreads per k-tile.
#define KC 64
#define ASTRIDE 72                    // fp16 elems per smem row (144B) — conflict-free LDSM
#define TILEE (128 * ASTRIDE)         // 9216 elems per array tile
#define TILE_B (TILEE * 2)            // 18432 bytes
#define NARR 4                        // sHi, s2 | gg, hh
#define STAGE_B (NARR * TILE_B)       // 73728 B per stage
#define NSTAGE 3
#define NKT (LL / KC)                 // 16
#define SMEM_MAIN (NSTAGE * STAGE_B)  // 221184 B

__device__ __forceinline__ void load_stage_m(uint32_t sstage, int i0, int j0, int k0, int t) {
    const int c = t & 7;              // 16B chunk within 128B of k
    const int r0 = t >> 3;            // 0..31
    const __half* srcs[NARR] = {g_sHi, g_s2, g_gg, g_hh};
#pragma unroll
    for (int a = 0; a < NARR; ++a) {
        const int base = (a < 2) ? i0 : j0;
        const __half* g = srcs[a] + (size_t)(base + r0) * LL + k0 + c * 8;
        const uint32_t sa = sstage + a * TILE_B + r0 * (ASTRIDE * 2) + c * 16;
#pragma unroll
        for (int e = 0; e < 4; ++e)
            cp16b(sa + e * 32 * (ASTRIDE * 2), g + (size_t)e * 32 * LL);
    }
}

__global__ __launch_bounds__(256, 1) void k_main(float* __restrict__ out) {
    extern __shared__ __half sm[];
    const uint32_t sbase = smem_u32(sm);
    const int t = threadIdx.x;
    const int lane = t & 31, wid = t >> 5;
    const int wm = wid >> 2, wn = wid & 3;     // 2x4 warp grid, warp tile 64x32
    const int lr = lane >> 2, lc = lane & 3;
    const int i0 = blockIdx.y * 128, j0 = blockIdx.x * 128;

    float numer[4][4][4], denom[4][4][4];
#pragma unroll
    for (int a = 0; a < 4; ++a)
#pragma unroll
        for (int b = 0; b < 4; ++b)
#pragma unroll
            for (int c = 0; c < 4; ++c) { numer[a][b][c] = 0.f; denom[a][b][c] = 0.f; }

    const int a_row_l = lane & 15;
    const int a_col_l = (lane >> 4) * 8;
    const int b_row_l = (lane & 7) + ((lane >> 4) << 3);
    const int b_col_l = ((lane >> 3) & 1) * 8;

    // prologue: stages for kt=0,1 into buffers 0,1
    load_stage_m(sbase + 0 * STAGE_B, i0, j0, 0 * KC, t);
    asm volatile("cp.async.commit_group;");
    load_stage_m(sbase + 1 * STAGE_B, i0, j0, 1 * KC, t);
    asm volatile("cp.async.commit_group;");

    int stC = 0;   // compute buffer for current kt
#pragma unroll 1
    for (int kt = 0; kt < NKT; ++kt) {
        // own group kt complete (at most 1 younger group outstanding)
        if (kt + 1 < NKT) asm volatile("cp.async.wait_group 1;");
        else              asm volatile("cp.async.wait_group 0;");
        // all threads have stage kt data; all warps finished reading stage kt-1
        __syncthreads();
        // prefetch kt+2 into buffer (kt+2)%3 == (kt-1)%3 — safe after the barrier
        if (kt + 2 < NKT) {
            int stW = stC + 2; if (stW >= NSTAGE) stW -= NSTAGE;
            load_stage_m(sbase + stW * STAGE_B, i0, j0, (kt + 2) * KC, t);
            asm volatile("cp.async.commit_group;");
        }

        const uint32_t sb = sbase + stC * STAGE_B;
#pragma unroll
        for (int kh = 0; kh < 4; ++kh) {
            const int kofs = kh * 16;
            uint32_t BG[2][4], BH[2][4];
#pragma unroll
            for (int n2 = 0; n2 < 2; ++n2) {
                const int brow = wn * 32 + n2 * 16 + b_row_l;
                const uint32_t bo = (uint32_t)(brow * ASTRIDE + kofs + b_col_l) * 2;
                ldsm4(BG[n2], sb + 2 * TILE_B + bo);
                ldsm4(BH[n2], sb + 3 * TILE_B + bo);
            }
            uint32_t A[2][2][4];   // [buf][sHi/s2][frag] — software-pipelined
            {
                const int arow = wm * 64 + a_row_l;
                const uint32_t ao = (uint32_t)(arow * ASTRIDE + kofs + a_col_l) * 2;
                ldsm4(A[0][0], sb + 0 * TILE_B + ao);
                ldsm4(A[0][1], sb + 1 * TILE_B + ao);
            }
#pragma unroll
            for (int mt = 0; mt < 4; ++mt) {
                if (mt < 3) {   // prefetch next mt's fragments under current MMAs
                    const int arow = wm * 64 + (mt + 1) * 16 + a_row_l;
                    const uint32_t ao = (uint32_t)(arow * ASTRIDE + kofs + a_col_l) * 2;
                    ldsm4(A[(mt + 1) & 1][0], sb + 0 * TILE_B + ao);
                    ldsm4(A[(mt + 1) & 1][1], sb + 1 * TILE_B + ao);
                }
                const int bf = mt & 1;
#pragma unroll
                for (int nt = 0; nt < 4; ++nt)
                    mma_f16(numer[mt][nt], A[bf][0], BG[nt >> 1][2 * (nt & 1)], BG[nt >> 1][2 * (nt & 1) + 1]);
#pragma unroll
                for (int nt = 0; nt < 4; ++nt)
                    mma_f16(denom[mt][nt], A[bf][1], BH[nt >> 1][2 * (nt & 1)], BH[nt >> 1][2 * (nt & 1) + 1]);
            }
        }
        stC = (stC + 1 == NSTAGE) ? 0 : stC + 1;
    }

    // epilogue
#pragma unroll
    for (int mt = 0; mt < 4; ++mt)
#pragma unroll
        for (int nt = 0; nt < 4; ++nt) {
            const int i = i0 + wm * 64 + mt * 16 + lr;
            const int j = j0 + wn * 32 + nt * 8 + lc * 2;
            float2 v0, v1;
            v0.x = numer[mt][nt][0] * rsqrtf(denom[mt][nt][0]);
            v0.y = numer[mt][nt][1] * rsqrtf(denom[mt][nt][1]);
            v1.x = numer[mt][nt][2] * rsqrtf(denom[mt][nt][2]);
            v1.y = numer[mt][nt][3] * rsqrtf(denom[mt][nt][3]);
            *reinterpret_cast<float2*>(out + (size_t)i * BSZ + j) = v0;
            *reinterpret_cast<float2*>(out + (size_t)(i + 8) * BSZ + j) = v1;
        }
}

// ---------------- launch ----------------
extern "C" void kernel_launch(void* const* d_in, const int* in_sizes, int n_in,
                              void* d_out, int out_size) {
    (void)in_sizes; (void)n_in; (void)out_size;
    const float* img  = (const float*)d_in[0];
    const float* cap  = (const float*)d_in[1];
    // d_in[2] = lens : unused by the reference computation
    const float* Wred = (const float*)d_in[3];
    const float* bred = (const float*)d_in[4];
    const float* Wkp  = (const float*)d_in[5];
    const float* bkp  = (const float*)d_in[6];
    float* out = (float*)d_out;

    k_sum<<<BSZ, 256>>>(img);
    k_norm<<<BSZ, 256>>>(cap);
    k_repr<<<BSZ / 8, 256>>>(cap, Wred, bred);
    k_wsplit<<<(LL * LK / 4) / 256, 256>>>(Wkp);

    cudaFuncSetAttribute(k_gate, cudaFuncAttributeMaxDynamicSharedMemorySize, SMEM_GATE);
    k_gate<<<dim3(LL / 128, BSZ / 128), 256, SMEM_GATE>>>(cap, bkp);

    cudaFuncSetAttribute(k_main, cudaFuncAttributeMaxDynamicSharedMemorySize, SMEM_MAIN);
    k_main<<<dim3(BSZ / 128, BSZ / 128), 256, SMEM_MAIN>>>(out);
}